// round 1
// baseline (speedup 1.0000x reference)
#include <cuda_runtime.h>
#include <cuda_bf16.h>
#include <math_constants.h>

// ---------------- problem constants ----------------
constexpr int B_    = 2;
constexpr int T_    = 2048;
constexpr int C_    = 2048;
constexpr int NH    = 16;
constexpr int NKV   = 4;
constexpr int HEADD = 128;          // C_/NH
constexpr int GROUP = NH / NKV;     // 4
constexpr int KVC   = NKV * HEADD;  // 512
constexpr int M_    = B_ * T_;      // 4096 rows for all GEMMs

__device__ float g_Q[(size_t)B_ * T_ * C_];    // (B,T,H*D)
__device__ float g_K[(size_t)B_ * T_ * KVC];   // (B,T,KV*D)
__device__ float g_V[(size_t)B_ * T_ * KVC];
__device__ float g_Y[(size_t)B_ * T_ * C_];    // attention out, (B,T,H*D)

// ---------------- SGEMM: C = A(MxK) * B(KxN), row-major ----------------
constexpr int GBM = 128, GBN = 128, GBK = 16;

__global__ __launch_bounds__(256, 2)
void sgemm_kernel(const float* __restrict__ A, const float* __restrict__ B,
                  float* __restrict__ C, int M, int N, int K) {
    __shared__ float As[GBK][GBM];
    __shared__ float Bs[GBK][GBN];

    const int tid = threadIdx.x;
    const int tx  = tid & 15;   // 0..15
    const int ty  = tid >> 4;   // 0..15
    const int row0 = blockIdx.y * GBM;
    const int col0 = blockIdx.x * GBN;

    float c[8][8];
    #pragma unroll
    for (int i = 0; i < 8; i++)
        #pragma unroll
        for (int j = 0; j < 8; j++) c[i][j] = 0.f;

    for (int k0 = 0; k0 < K; k0 += GBK) {
        // load A tile (GBM x GBK) -> As[k][m]   (512 float4s, 2 per thread)
        #pragma unroll
        for (int i = 0; i < 2; i++) {
            int f  = tid + i * 256;
            int m  = f >> 2;            // 0..127
            int k4 = (f & 3) * 4;       // 0,4,8,12
            float4 a = *(const float4*)&A[(size_t)(row0 + m) * K + k0 + k4];
            As[k4 + 0][m] = a.x;
            As[k4 + 1][m] = a.y;
            As[k4 + 2][m] = a.z;
            As[k4 + 3][m] = a.w;
        }
        // load B tile (GBK x GBN) -> Bs[k][n]
        #pragma unroll
        for (int i = 0; i < 2; i++) {
            int f  = tid + i * 256;
            int kk = f >> 5;            // 0..15
            int n4 = (f & 31) * 4;      // 0..124
            *(float4*)&Bs[kk][n4] =
                *(const float4*)&B[(size_t)(k0 + kk) * N + col0 + n4];
        }
        __syncthreads();

        #pragma unroll
        for (int kk = 0; kk < GBK; kk++) {
            float a[8], b[8];
            *(float4*)&a[0] = *(const float4*)&As[kk][ty * 4];
            *(float4*)&a[4] = *(const float4*)&As[kk][64 + ty * 4];
            *(float4*)&b[0] = *(const float4*)&Bs[kk][tx * 4];
            *(float4*)&b[4] = *(const float4*)&Bs[kk][64 + tx * 4];
            #pragma unroll
            for (int i = 0; i < 8; i++)
                #pragma unroll
                for (int j = 0; j < 8; j++)
                    c[i][j] = fmaf(a[i], b[j], c[i][j]);
        }
        __syncthreads();
    }

    #pragma unroll
    for (int i = 0; i < 8; i++) {
        int m = row0 + ((i < 4) ? (ty * 4 + i) : (64 + ty * 4 + (i - 4)));
        float4 v0 = make_float4(c[i][0], c[i][1], c[i][2], c[i][3]);
        float4 v1 = make_float4(c[i][4], c[i][5], c[i][6], c[i][7]);
        *(float4*)&C[(size_t)m * N + col0 + tx * 4]      = v0;
        *(float4*)&C[(size_t)m * N + col0 + 64 + tx * 4] = v1;
    }
}

// ---------------- causal GQA flash attention (fp32) ----------------
// Grid: (T/QT, NH, B). Block: 256 threads = 64 rows x 4 d-slices (32 cols each).
constexpr int QT = 64;
constexpr int KT = 64;
constexpr int SPITCH = KT + 1;                 // padded score row
constexpr int ATTN_SMEM =
    (QT * HEADD + KT * HEADD + KT * HEADD + QT * SPITCH) * (int)sizeof(float);

__global__ __launch_bounds__(256, 1)
void attn_kernel(const float* __restrict__ Q, const float* __restrict__ K,
                 const float* __restrict__ V, float* __restrict__ Y) {
    extern __shared__ float sm[];
    float* sQ = sm;                      // QT x HEADD
    float* sK = sQ + QT * HEADD;         // KT x HEADD
    float* sV = sK + KT * HEADD;         // KT x HEADD
    float* sS = sV + KT * HEADD;         // QT x SPITCH

    const int qtile = blockIdx.x;
    const int h     = blockIdx.y;
    const int b     = blockIdx.z;
    const int kvh   = h / GROUP;
    const int q0    = qtile * QT;
    const int tid   = threadIdx.x;
    const int r     = tid >> 2;          // q row within tile: 0..63
    const int s     = tid & 3;           // d-slice: 0..3 (32 cols each)
    const float scale = 0.0883883476483184405f;  // 1/sqrt(128)

    // load Q tile: Q[(b*T + q0+rr)*C + h*128 + d]
    for (int i = tid; i < QT * (HEADD / 4); i += 256) {
        int rr = i / (HEADD / 4);
        int d4 = i % (HEADD / 4);
        *(float4*)&sQ[rr * HEADD + d4 * 4] =
            *(const float4*)&Q[((size_t)(b * T_ + q0 + rr)) * C_ + h * HEADD + d4 * 4];
    }

    float m_run = -CUDART_INF_F;
    float l_run = 0.f;
    float acc[32];
    #pragma unroll
    for (int d = 0; d < 32; d++) acc[d] = 0.f;

    const float4* qv = (const float4*)(sQ + r * HEADD);

    for (int j = 0; j <= qtile; j++) {
        const int k0 = j * KT;
        __syncthreads();  // protect sS/sV reads of previous tile (and Q load, 1st iter)

        // load K/V tiles: [(b*T + k0+kk)*KVC + kvh*128 + d]
        for (int i = tid; i < KT * (HEADD / 4); i += 256) {
            int kk = i / (HEADD / 4);
            int d4 = i % (HEADD / 4);
            size_t gbase = ((size_t)(b * T_ + k0 + kk)) * KVC + kvh * HEADD + d4 * 4;
            *(float4*)&sK[kk * HEADD + d4 * 4] = *(const float4*)&K[gbase];
            *(float4*)&sV[kk * HEADD + d4 * 4] = *(const float4*)&V[gbase];
        }
        __syncthreads();

        // scores: this thread computes keys [s*16, s*16+16) for row r
        {
            float sc[16];
            #pragma unroll
            for (int kk = 0; kk < 16; kk++) sc[kk] = 0.f;
            #pragma unroll 8
            for (int d4 = 0; d4 < HEADD / 4; d4++) {
                float4 qq = qv[d4];
                #pragma unroll
                for (int kk = 0; kk < 16; kk++) {
                    float4 kv4 = ((const float4*)(sK + (s * 16 + kk) * HEADD))[d4];
                    sc[kk] = fmaf(qq.x, kv4.x,
                             fmaf(qq.y, kv4.y,
                             fmaf(qq.z, kv4.z,
                             fmaf(qq.w, kv4.w, sc[kk]))));
                }
            }
            const int q_abs = q0 + r;
            #pragma unroll
            for (int kk = 0; kk < 16; kk++) {
                int key = k0 + s * 16 + kk;
                sS[r * SPITCH + s * 16 + kk] =
                    (key > q_abs) ? -CUDART_INF_F : sc[kk] * scale;
            }
        }
        __syncthreads();

        // online softmax update (each of 4 threads per row redundantly reduces)
        float mt = -CUDART_INF_F;
        #pragma unroll 8
        for (int kk = 0; kk < KT; kk++) mt = fmaxf(mt, sS[r * SPITCH + kk]);
        float m_new = fmaxf(m_run, mt);
        float corr  = __expf(m_run - m_new);   // 0 when m_run = -inf
        #pragma unroll
        for (int d = 0; d < 32; d++) acc[d] *= corr;

        float lt = 0.f;
        for (int kk = 0; kk < KT; kk++) {
            float p = __expf(sS[r * SPITCH + kk] - m_new);
            lt += p;
            const float4* vrow = (const float4*)(sV + kk * HEADD + s * 32);
            #pragma unroll
            for (int d4 = 0; d4 < 8; d4++) {
                float4 vv = vrow[d4];
                acc[d4 * 4 + 0] = fmaf(p, vv.x, acc[d4 * 4 + 0]);
                acc[d4 * 4 + 1] = fmaf(p, vv.y, acc[d4 * 4 + 1]);
                acc[d4 * 4 + 2] = fmaf(p, vv.z, acc[d4 * 4 + 2]);
                acc[d4 * 4 + 3] = fmaf(p, vv.w, acc[d4 * 4 + 3]);
            }
        }
        l_run = l_run * corr + lt;
        m_run = m_new;
    }

    // write out: Y[(b*T + q)*C + h*128 + s*32 + d]
    const float inv_l = 1.f / l_run;
    float* yout = &Y[((size_t)(b * T_ + q0 + r)) * C_ + h * HEADD + s * 32];
    #pragma unroll
    for (int d4 = 0; d4 < 8; d4++) {
        float4 o = make_float4(acc[d4 * 4 + 0] * inv_l, acc[d4 * 4 + 1] * inv_l,
                               acc[d4 * 4 + 2] * inv_l, acc[d4 * 4 + 3] * inv_l);
        *(float4*)&yout[d4 * 4] = o;
    }
}

// ---------------- launch ----------------
extern "C" void kernel_launch(void* const* d_in, const int* in_sizes, int n_in,
                              void* d_out, int out_size) {
    const float* x  = (const float*)d_in[0];
    const float* Wq = (const float*)d_in[1];
    const float* Wk = (const float*)d_in[2];
    const float* Wv = (const float*)d_in[3];
    const float* Wo = (const float*)d_in[4];
    float* out = (float*)d_out;

    float *Qb, *Kb, *Vb, *Yb;
    cudaGetSymbolAddress((void**)&Qb, g_Q);
    cudaGetSymbolAddress((void**)&Kb, g_K);
    cudaGetSymbolAddress((void**)&Vb, g_V);
    cudaGetSymbolAddress((void**)&Yb, g_Y);

    cudaFuncSetAttribute(attn_kernel, cudaFuncAttributeMaxDynamicSharedMemorySize,
                         ATTN_SMEM);

    dim3 blk(256);
    dim3 gQ(C_ / GBN, M_ / GBM);    // 16 x 32
    dim3 gKV(KVC / GBN, M_ / GBM);  // 4 x 32

    sgemm_kernel<<<gQ,  blk>>>(x, Wq, Qb, M_, C_,  C_);
    sgemm_kernel<<<gKV, blk>>>(x, Wk, Kb, M_, KVC, C_);
    sgemm_kernel<<<gKV, blk>>>(x, Wv, Vb, M_, KVC, C_);

    dim3 ga(T_ / QT, NH, B_);       // 32 x 16 x 2
    attn_kernel<<<ga, blk, ATTN_SMEM>>>(Qb, Kb, Vb, Yb);

    sgemm_kernel<<<gQ, blk>>>(Yb, Wo, out, M_, C_, C_);
}

// round 4
// speedup vs baseline: 1.1369x; 1.1369x over previous
#include <cuda_runtime.h>
#include <cuda_bf16.h>
#include <math_constants.h>
#include <cstdint>

// ---------------- problem constants ----------------
constexpr int B_    = 2;
constexpr int T_    = 2048;
constexpr int C_    = 2048;
constexpr int NH    = 16;
constexpr int NKV   = 4;
constexpr int HEADD = 128;          // C_/NH
constexpr int GROUP = NH / NKV;     // 4
constexpr int KVC   = NKV * HEADD;  // 512
constexpr int M_    = B_ * T_;      // 4096 rows for all GEMMs

// ---------------- scratch (device globals; no allocation) ----------------
__device__ float g_Q[(size_t)M_ * C_];     // (B,T,H*D) fp32
__device__ float g_K[(size_t)M_ * KVC];
__device__ float g_V[(size_t)M_ * KVC];
__device__ float g_Y[(size_t)M_ * C_];     // attention out fp32

__device__ __nv_bfloat16 g_xh[(size_t)M_ * C_],  g_xl[(size_t)M_ * C_];
__device__ __nv_bfloat16 g_yh[(size_t)M_ * C_],  g_yl[(size_t)M_ * C_];
__device__ __nv_bfloat16 g_wqh[(size_t)C_ * C_], g_wql[(size_t)C_ * C_];   // [N][K] k-major
__device__ __nv_bfloat16 g_wkh[(size_t)KVC * C_], g_wkl[(size_t)KVC * C_];
__device__ __nv_bfloat16 g_wvh[(size_t)KVC * C_], g_wvl[(size_t)KVC * C_];
__device__ __nv_bfloat16 g_woh[(size_t)C_ * C_], g_wol[(size_t)C_ * C_];

// ---------------- PTX helpers (baseline, arch-agnostic) ----------------
__device__ __forceinline__ uint32_t smem_u32(const void* p) {
    uint32_t a;
    asm("{ .reg .u64 t; cvta.to.shared.u64 t, %1; cvt.u32.u64 %0, t; }" : "=r"(a) : "l"(p));
    return a;
}
#define CP_COMMIT()   asm volatile("cp.async.commit_group;" ::: "memory")
#define CP_WAIT(n)    asm volatile("cp.async.wait_group %0;" :: "n"(n) : "memory")
__device__ __forceinline__ void cp16(uint32_t dst, const void* src) {
    asm volatile("cp.async.cg.shared.global [%0], [%1], 16;" :: "r"(dst), "l"(src));
}
__device__ __forceinline__ void ldm_x4(uint32_t* r, uint32_t addr) {
    asm volatile("ldmatrix.sync.aligned.m8n8.x4.shared.b16 {%0,%1,%2,%3}, [%4];"
        : "=r"(r[0]), "=r"(r[1]), "=r"(r[2]), "=r"(r[3]) : "r"(addr));
}
__device__ __forceinline__ void mma16816(float* d, const uint32_t* a, const uint32_t* b) {
    asm volatile("mma.sync.aligned.m16n8k16.row.col.f32.bf16.bf16.f32 "
        "{%0,%1,%2,%3}, {%4,%5,%6,%7}, {%8,%9}, {%0,%1,%2,%3};"
        : "+f"(d[0]), "+f"(d[1]), "+f"(d[2]), "+f"(d[3])
        : "r"(a[0]), "r"(a[1]), "r"(a[2]), "r"(a[3]), "r"(b[0]), "r"(b[1]));
}

// ---------------- conversion kernels ----------------
__global__ void split_kernel(const float* __restrict__ in, __nv_bfloat16* __restrict__ hi,
                             __nv_bfloat16* __restrict__ lo, int n4) {
    int i = blockIdx.x * 256 + threadIdx.x;
    if (i >= n4) return;
    float4 v = ((const float4*)in)[i];
    float vs[4] = {v.x, v.y, v.z, v.w};
    __nv_bfloat16 h[4], l[4];
    #pragma unroll
    for (int j = 0; j < 4; j++) {
        h[j] = __float2bfloat16(vs[j]);
        l[j] = __float2bfloat16(vs[j] - __bfloat162float(h[j]));
    }
    ((__nv_bfloat162*)hi)[2 * i]     = __halves2bfloat162(h[0], h[1]);
    ((__nv_bfloat162*)hi)[2 * i + 1] = __halves2bfloat162(h[2], h[3]);
    ((__nv_bfloat162*)lo)[2 * i]     = __halves2bfloat162(l[0], l[1]);
    ((__nv_bfloat162*)lo)[2 * i + 1] = __halves2bfloat162(l[2], l[3]);
}

// W (K x N fp32, row-major) -> Wt_hi/lo (N x K bf16, row-major)
__global__ void split_transpose_kernel(const float* __restrict__ W,
                                       __nv_bfloat16* __restrict__ th,
                                       __nv_bfloat16* __restrict__ tl, int K, int N) {
    __shared__ float tile[32][33];
    int n0 = blockIdx.x * 32, k0 = blockIdx.y * 32;
    int tx = threadIdx.x, ty = threadIdx.y;  // 32 x 8
    #pragma unroll
    for (int i = 0; i < 32; i += 8)
        tile[ty + i][tx] = W[(size_t)(k0 + ty + i) * N + n0 + tx];
    __syncthreads();
    #pragma unroll
    for (int i = 0; i < 32; i += 8) {
        float v = tile[tx][ty + i];
        __nv_bfloat16 h = __float2bfloat16(v);
        __nv_bfloat16 l = __float2bfloat16(v - __bfloat162float(h));
        size_t o = (size_t)(n0 + ty + i) * K + k0 + tx;
        th[o] = h;
        tl[o] = l;
    }
}

// ---------------- split-bf16 GEMM via mma.sync (HMMA.16816) ----------------
// C[m,n] = sum_k A[m,k]*Bt[n,k]; A = Ah+Al, Bt = Bh+Bl, both K-major bf16.
// CTA tile 128x128, BK=32, 8 warps (2x4), warp tile 64x32, double-buffered cp.async.
constexpr int BK       = 32;
constexpr int PITCH    = 80;                 // bytes per 32-bf16 row (64B data + 16B pad)
constexpr int TILE_BYT = 128 * PITCH;        // 10240
constexpr int STAGE_BYT = 4 * TILE_BYT;      // Ah, Al, Bh, Bl = 40960
constexpr int GEMM_SMEM = 2 * STAGE_BYT;     // 81920

__global__ __launch_bounds__(256, 2)
void tc_gemm(const __nv_bfloat16* __restrict__ Ah, const __nv_bfloat16* __restrict__ Al,
             const __nv_bfloat16* __restrict__ Bh, const __nv_bfloat16* __restrict__ Bl,
             float* __restrict__ C, int Ncols, int K) {
    extern __shared__ __align__(128) char smem[];
    const uint32_t sbase = smem_u32(smem);
    const int tid  = threadIdx.x;
    const int wid  = tid >> 5, lane = tid & 31;
    const int wm   = wid & 1;            // 0..1  -> m offset 64*wm
    const int wn   = wid >> 1;           // 0..3  -> n offset 32*wn
    const int m0   = blockIdx.y * 128, n0 = blockIdx.x * 128;

    // lane-dependent ldmatrix address components
    const uint32_t aoff = (uint32_t)(lane & 15) * PITCH + (uint32_t)(lane >> 4) * 16;
    const uint32_t boff = (uint32_t)((lane & 7) + ((lane >> 4) & 1) * 8) * PITCH +
                          (uint32_t)((lane >> 3) & 1) * 16;

    float acc[4][4][4];
    #pragma unroll
    for (int i = 0; i < 4; i++)
        #pragma unroll
        for (int j = 0; j < 4; j++)
            #pragma unroll
            for (int q = 0; q < 4; q++) acc[i][j][q] = 0.f;

    const int NS = K / BK;
    const int lr = tid >> 2;       // load row   0..63   (x2 passes -> 128)
    const int lc = tid & 3;        // load chunk 0..3 (16B)

    auto load_stage = [&](int s, int b) {
        uint32_t base = sbase + (uint32_t)b * STAGE_BYT;
        const int k0 = s * BK;
        const __nv_bfloat16* srcs[4] = {Ah, Al, Bh, Bl};
        const int rows[4] = {m0, m0, n0, n0};
        #pragma unroll
        for (int t = 0; t < 4; t++) {
            uint32_t tb = base + (uint32_t)t * TILE_BYT;
            #pragma unroll
            for (int p = 0; p < 2; p++) {
                int r = lr + p * 64;
                cp16(tb + (uint32_t)r * PITCH + (uint32_t)lc * 16,
                     (const char*)(srcs[t] + (size_t)(rows[t] + r) * K + k0) + lc * 16);
            }
        }
        CP_COMMIT();
    };

    load_stage(0, 0);

    for (int i = 0; i < NS; ++i) {
        const int buf = i & 1;
        if (i + 1 < NS) { load_stage(i + 1, buf ^ 1); CP_WAIT(1); }
        else           { CP_WAIT(0); }
        __syncthreads();

        const uint32_t base = sbase + (uint32_t)buf * STAGE_BYT;
        const uint32_t aH = base, aL = base + TILE_BYT;
        const uint32_t bH = base + 2 * TILE_BYT, bL = base + 3 * TILE_BYT;
        const uint32_t arow = (uint32_t)(wm * 64) * PITCH;
        const uint32_t brow = (uint32_t)(wn * 32) * PITCH;

        #pragma unroll
        for (int kk = 0; kk < 2; ++kk) {
            const uint32_t kb = (uint32_t)kk * 32;
            uint32_t af[4][4], bf[4][2];

            // Ah frags
            #pragma unroll
            for (int mi = 0; mi < 4; mi++)
                ldm_x4(af[mi], aH + arow + (uint32_t)(mi * 16) * PITCH + kb + aoff);
            // Bh frags (two n-pairs)
            #pragma unroll
            for (int np = 0; np < 2; np++) {
                uint32_t t[4];
                ldm_x4(t, bH + brow + (uint32_t)(np * 16) * PITCH + kb + boff);
                bf[2 * np][0] = t[0]; bf[2 * np][1] = t[1];
                bf[2 * np + 1][0] = t[2]; bf[2 * np + 1][1] = t[3];
            }
            #pragma unroll
            for (int mi = 0; mi < 4; mi++)
                #pragma unroll
                for (int ni = 0; ni < 4; ni++)
                    mma16816(acc[mi][ni], af[mi], bf[ni]);

            // Bl frags (overwrite bf) -> Ah * Bl
            #pragma unroll
            for (int np = 0; np < 2; np++) {
                uint32_t t[4];
                ldm_x4(t, bL + brow + (uint32_t)(np * 16) * PITCH + kb + boff);
                bf[2 * np][0] = t[0]; bf[2 * np][1] = t[1];
                bf[2 * np + 1][0] = t[2]; bf[2 * np + 1][1] = t[3];
            }
            #pragma unroll
            for (int mi = 0; mi < 4; mi++)
                #pragma unroll
                for (int ni = 0; ni < 4; ni++)
                    mma16816(acc[mi][ni], af[mi], bf[ni]);

            // Al frags (overwrite af), reload Bh -> Al * Bh
            #pragma unroll
            for (int mi = 0; mi < 4; mi++)
                ldm_x4(af[mi], aL + arow + (uint32_t)(mi * 16) * PITCH + kb + aoff);
            #pragma unroll
            for (int np = 0; np < 2; np++) {
                uint32_t t[4];
                ldm_x4(t, bH + brow + (uint32_t)(np * 16) * PITCH + kb + boff);
                bf[2 * np][0] = t[0]; bf[2 * np][1] = t[1];
                bf[2 * np + 1][0] = t[2]; bf[2 * np + 1][1] = t[3];
            }
            #pragma unroll
            for (int mi = 0; mi < 4; mi++)
                #pragma unroll
                for (int ni = 0; ni < 4; ni++)
                    mma16816(acc[mi][ni], af[mi], bf[ni]);
        }
        __syncthreads();
    }

    // epilogue: c0/c1 at (row, col..col+1), c2/c3 at (row+8, col..col+1)
    const int rbase = m0 + wm * 64 + (lane >> 2);
    const int cbase = n0 + wn * 32 + (lane & 3) * 2;
    #pragma unroll
    for (int mi = 0; mi < 4; mi++) {
        #pragma unroll
        for (int ni = 0; ni < 4; ni++) {
            int row = rbase + mi * 16;
            int col = cbase + ni * 8;
            *(float2*)&C[(size_t)row * Ncols + col] =
                make_float2(acc[mi][ni][0], acc[mi][ni][1]);
            *(float2*)&C[(size_t)(row + 8) * Ncols + col] =
                make_float2(acc[mi][ni][2], acc[mi][ni][3]);
        }
    }
}

// ---------------- causal GQA flash attention (fp32) ----------------
constexpr int QT = 64;
constexpr int KT = 64;
constexpr int SPITCH = KT + 1;
constexpr int ATTN_SMEM =
    (QT * HEADD + KT * HEADD + KT * HEADD + QT * SPITCH) * (int)sizeof(float);

__global__ __launch_bounds__(256, 1)
void attn_kernel(const float* __restrict__ Q, const float* __restrict__ K,
                 const float* __restrict__ V, float* __restrict__ Y) {
    extern __shared__ float sm[];
    float* sQ = sm;
    float* sK = sQ + QT * HEADD;
    float* sV = sK + KT * HEADD;
    float* sS = sV + KT * HEADD;

    const int qtile = blockIdx.x;
    const int h     = blockIdx.y;
    const int b     = blockIdx.z;
    const int kvh   = h / GROUP;
    const int q0    = qtile * QT;
    const int tid   = threadIdx.x;
    const int r     = tid >> 2;
    const int s     = tid & 3;
    const float scale = 0.0883883476483184405f;

    for (int i = tid; i < QT * (HEADD / 4); i += 256) {
        int rr = i / (HEADD / 4);
        int d4 = i % (HEADD / 4);
        *(float4*)&sQ[rr * HEADD + d4 * 4] =
            *(const float4*)&Q[((size_t)(b * T_ + q0 + rr)) * C_ + h * HEADD + d4 * 4];
    }

    float m_run = -CUDART_INF_F;
    float l_run = 0.f;
    float acc[32];
    #pragma unroll
    for (int d = 0; d < 32; d++) acc[d] = 0.f;

    const float4* qv = (const float4*)(sQ + r * HEADD);

    for (int j = 0; j <= qtile; j++) {
        const int k0 = j * KT;
        __syncthreads();

        for (int i = tid; i < KT * (HEADD / 4); i += 256) {
            int kk = i / (HEADD / 4);
            int d4 = i % (HEADD / 4);
            size_t gbase = ((size_t)(b * T_ + k0 + kk)) * KVC + kvh * HEADD + d4 * 4;
            *(float4*)&sK[kk * HEADD + d4 * 4] = *(const float4*)&K[gbase];
            *(float4*)&sV[kk * HEADD + d4 * 4] = *(const float4*)&V[gbase];
        }
        __syncthreads();

        {
            float sc[16];
            #pragma unroll
            for (int kk = 0; kk < 16; kk++) sc[kk] = 0.f;
            #pragma unroll 8
            for (int d4 = 0; d4 < HEADD / 4; d4++) {
                float4 qq = qv[d4];
                #pragma unroll
                for (int kk = 0; kk < 16; kk++) {
                    float4 kv4 = ((const float4*)(sK + (s * 16 + kk) * HEADD))[d4];
                    sc[kk] = fmaf(qq.x, kv4.x,
                             fmaf(qq.y, kv4.y,
                             fmaf(qq.z, kv4.z,
                             fmaf(qq.w, kv4.w, sc[kk]))));
                }
            }
            const int q_abs = q0 + r;
            #pragma unroll
            for (int kk = 0; kk < 16; kk++) {
                int key = k0 + s * 16 + kk;
                sS[r * SPITCH + s * 16 + kk] =
                    (key > q_abs) ? -CUDART_INF_F : sc[kk] * scale;
            }
        }
        __syncthreads();

        float mt = -CUDART_INF_F;
        #pragma unroll 8
        for (int kk = 0; kk < KT; kk++) mt = fmaxf(mt, sS[r * SPITCH + kk]);
        float m_new = fmaxf(m_run, mt);
        float corr  = __expf(m_run - m_new);
        #pragma unroll
        for (int d = 0; d < 32; d++) acc[d] *= corr;

        float lt = 0.f;
        for (int kk = 0; kk < KT; kk++) {
            float p = __expf(sS[r * SPITCH + kk] - m_new);
            lt += p;
            const float4* vrow = (const float4*)(sV + kk * HEADD + s * 32);
            #pragma unroll
            for (int d4 = 0; d4 < 8; d4++) {
                float4 vv = vrow[d4];
                acc[d4 * 4 + 0] = fmaf(p, vv.x, acc[d4 * 4 + 0]);
                acc[d4 * 4 + 1] = fmaf(p, vv.y, acc[d4 * 4 + 1]);
                acc[d4 * 4 + 2] = fmaf(p, vv.z, acc[d4 * 4 + 2]);
                acc[d4 * 4 + 3] = fmaf(p, vv.w, acc[d4 * 4 + 3]);
            }
        }
        l_run = l_run * corr + lt;
        m_run = m_new;
    }

    const float inv_l = 1.f / l_run;
    float* yout = &Y[((size_t)(b * T_ + q0 + r)) * C_ + h * HEADD + s * 32];
    #pragma unroll
    for (int d4 = 0; d4 < 8; d4++) {
        float4 o = make_float4(acc[d4 * 4 + 0] * inv_l, acc[d4 * 4 + 1] * inv_l,
                               acc[d4 * 4 + 2] * inv_l, acc[d4 * 4 + 3] * inv_l);
        *(float4*)&yout[d4 * 4] = o;
    }
}

// ---------------- launch ----------------
extern "C" void kernel_launch(void* const* d_in, const int* in_sizes, int n_in,
                              void* d_out, int out_size) {
    const float* x  = (const float*)d_in[0];
    const float* Wq = (const float*)d_in[1];
    const float* Wk = (const float*)d_in[2];
    const float* Wv = (const float*)d_in[3];
    const float* Wo = (const float*)d_in[4];
    float* out = (float*)d_out;

    float *Qb, *Kb, *Vb, *Yb;
    cudaGetSymbolAddress((void**)&Qb, g_Q);
    cudaGetSymbolAddress((void**)&Kb, g_K);
    cudaGetSymbolAddress((void**)&Vb, g_V);
    cudaGetSymbolAddress((void**)&Yb, g_Y);
    __nv_bfloat16 *xh, *xl, *yh, *yl, *wqh, *wql, *wkh, *wkl, *wvh, *wvl, *woh, *wol;
    cudaGetSymbolAddress((void**)&xh, g_xh);   cudaGetSymbolAddress((void**)&xl, g_xl);
    cudaGetSymbolAddress((void**)&yh, g_yh);   cudaGetSymbolAddress((void**)&yl, g_yl);
    cudaGetSymbolAddress((void**)&wqh, g_wqh); cudaGetSymbolAddress((void**)&wql, g_wql);
    cudaGetSymbolAddress((void**)&wkh, g_wkh); cudaGetSymbolAddress((void**)&wkl, g_wkl);
    cudaGetSymbolAddress((void**)&wvh, g_wvh); cudaGetSymbolAddress((void**)&wvl, g_wvl);
    cudaGetSymbolAddress((void**)&woh, g_woh); cudaGetSymbolAddress((void**)&wol, g_wol);

    cudaFuncSetAttribute(attn_kernel, cudaFuncAttributeMaxDynamicSharedMemorySize, ATTN_SMEM);
    cudaFuncSetAttribute(tc_gemm, cudaFuncAttributeMaxDynamicSharedMemorySize, GEMM_SMEM);

    // 1) split inputs / weights into bf16 hi/lo (weights transposed to K-major)
    {
        int n4 = M_ * C_ / 4;
        split_kernel<<<(n4 + 255) / 256, 256>>>(x, xh, xl, n4);
        dim3 tb(32, 8);
        split_transpose_kernel<<<dim3(C_ / 32,  C_ / 32), tb>>>(Wq, wqh, wql, C_, C_);
        split_transpose_kernel<<<dim3(KVC / 32, C_ / 32), tb>>>(Wk, wkh, wkl, C_, KVC);
        split_transpose_kernel<<<dim3(KVC / 32, C_ / 32), tb>>>(Wv, wvh, wvl, C_, KVC);
        split_transpose_kernel<<<dim3(C_ / 32,  C_ / 32), tb>>>(Wo, woh, wol, C_, C_);
    }

    // 2) projections on tensor cores (mma.sync)
    dim3 blk(256);
    tc_gemm<<<dim3(C_ / 128,  M_ / 128), blk, GEMM_SMEM>>>(xh, xl, wqh, wql, Qb, C_,  C_);
    tc_gemm<<<dim3(KVC / 128, M_ / 128), blk, GEMM_SMEM>>>(xh, xl, wkh, wkl, Kb, KVC, C_);
    tc_gemm<<<dim3(KVC / 128, M_ / 128), blk, GEMM_SMEM>>>(xh, xl, wvh, wvl, Vb, KVC, C_);

    // 3) attention
    dim3 ga(T_ / QT, NH, B_);
    attn_kernel<<<ga, blk, ATTN_SMEM>>>(Qb, Kb, Vb, Yb);

    // 4) output projection
    {
        int n4 = M_ * C_ / 4;
        split_kernel<<<(n4 + 255) / 256, 256>>>(Yb, yh, yl, n4);
    }
    tc_gemm<<<dim3(C_ / 128, M_ / 128), blk, GEMM_SMEM>>>(yh, yl, woh, wol, out, C_, C_);
}

// round 5
// speedup vs baseline: 8.9227x; 7.8482x over previous
#include <cuda_runtime.h>
#include <cuda_bf16.h>
#include <math_constants.h>
#include <cstdint>

// ---------------- problem constants ----------------
constexpr int B_    = 2;
constexpr int T_    = 2048;
constexpr int C_    = 2048;
constexpr int NH    = 16;
constexpr int NKV   = 4;
constexpr int HEADD = 128;          // C_/NH
constexpr int GROUP = NH / NKV;     // 4
constexpr int KVC   = NKV * HEADD;  // 512
constexpr int M_    = B_ * T_;      // 4096 rows for all GEMMs

// ---------------- scratch (device globals; no allocation) ----------------
__device__ __nv_bfloat16 g_xh[(size_t)M_ * C_],  g_xl[(size_t)M_ * C_];
__device__ __nv_bfloat16 g_qh[(size_t)M_ * C_],  g_ql[(size_t)M_ * C_];
__device__ __nv_bfloat16 g_kh[(size_t)M_ * KVC], g_kl[(size_t)M_ * KVC];
__device__ __nv_bfloat16 g_vh[(size_t)M_ * KVC], g_vl[(size_t)M_ * KVC];
__device__ __nv_bfloat16 g_yh[(size_t)M_ * C_],  g_yl[(size_t)M_ * C_];
__device__ __nv_bfloat16 g_wqh[(size_t)C_ * C_], g_wql[(size_t)C_ * C_];   // [N][K] k-major
__device__ __nv_bfloat16 g_wkh[(size_t)KVC * C_], g_wkl[(size_t)KVC * C_];
__device__ __nv_bfloat16 g_wvh[(size_t)KVC * C_], g_wvl[(size_t)KVC * C_];
__device__ __nv_bfloat16 g_woh[(size_t)C_ * C_], g_wol[(size_t)C_ * C_];

// ---------------- PTX helpers (baseline, arch-agnostic) ----------------
__device__ __forceinline__ uint32_t smem_u32(const void* p) {
    uint32_t a;
    asm("{ .reg .u64 t; cvta.to.shared.u64 t, %1; cvt.u32.u64 %0, t; }" : "=r"(a) : "l"(p));
    return a;
}
#define CP_COMMIT()   asm volatile("cp.async.commit_group;" ::: "memory")
#define CP_WAIT(n)    asm volatile("cp.async.wait_group %0;" :: "n"(n) : "memory")
__device__ __forceinline__ void cp16(uint32_t dst, const void* src) {
    asm volatile("cp.async.cg.shared.global [%0], [%1], 16;" :: "r"(dst), "l"(src));
}
__device__ __forceinline__ void ldm_x4(uint32_t* r, uint32_t addr) {
    asm volatile("ldmatrix.sync.aligned.m8n8.x4.shared.b16 {%0,%1,%2,%3}, [%4];"
        : "=r"(r[0]), "=r"(r[1]), "=r"(r[2]), "=r"(r[3]) : "r"(addr));
}
__device__ __forceinline__ void ldm_x4_t(uint32_t* r, uint32_t addr) {
    asm volatile("ldmatrix.sync.aligned.m8n8.x4.trans.shared.b16 {%0,%1,%2,%3}, [%4];"
        : "=r"(r[0]), "=r"(r[1]), "=r"(r[2]), "=r"(r[3]) : "r"(addr));
}
__device__ __forceinline__ void mma16816(float* d, const uint32_t* a, uint32_t b0, uint32_t b1) {
    asm volatile("mma.sync.aligned.m16n8k16.row.col.f32.bf16.bf16.f32 "
        "{%0,%1,%2,%3}, {%4,%5,%6,%7}, {%8,%9}, {%0,%1,%2,%3};"
        : "+f"(d[0]), "+f"(d[1]), "+f"(d[2]), "+f"(d[3])
        : "r"(a[0]), "r"(a[1]), "r"(a[2]), "r"(a[3]), "r"(b0), "r"(b1));
}
__device__ __forceinline__ float fast_ex2(float x) {
    float y;
    asm("ex2.approx.f32 %0, %1;" : "=f"(y) : "f"(x));
    return y;
}
__device__ __forceinline__ uint32_t pack_bf16(float a, float b) {
    __nv_bfloat162 v = __halves2bfloat162(__float2bfloat16(a), __float2bfloat16(b));
    return *(uint32_t*)&v;
}

// ---------------- conversion kernels ----------------
__global__ void split_kernel(const float* __restrict__ in, __nv_bfloat16* __restrict__ hi,
                             __nv_bfloat16* __restrict__ lo, int n4) {
    int i = blockIdx.x * 256 + threadIdx.x;
    if (i >= n4) return;
    float4 v = ((const float4*)in)[i];
    float vs[4] = {v.x, v.y, v.z, v.w};
    __nv_bfloat16 h[4], l[4];
    #pragma unroll
    for (int j = 0; j < 4; j++) {
        h[j] = __float2bfloat16(vs[j]);
        l[j] = __float2bfloat16(vs[j] - __bfloat162float(h[j]));
    }
    ((__nv_bfloat162*)hi)[2 * i]     = __halves2bfloat162(h[0], h[1]);
    ((__nv_bfloat162*)hi)[2 * i + 1] = __halves2bfloat162(h[2], h[3]);
    ((__nv_bfloat162*)lo)[2 * i]     = __halves2bfloat162(l[0], l[1]);
    ((__nv_bfloat162*)lo)[2 * i + 1] = __halves2bfloat162(l[2], l[3]);
}

// W (K x N fp32, row-major) -> Wt_hi/lo (N x K bf16, row-major)
__global__ void split_transpose_kernel(const float* __restrict__ W,
                                       __nv_bfloat16* __restrict__ th,
                                       __nv_bfloat16* __restrict__ tl, int K, int N) {
    __shared__ float tile[32][33];
    int n0 = blockIdx.x * 32, k0 = blockIdx.y * 32;
    int tx = threadIdx.x, ty = threadIdx.y;  // 32 x 8
    #pragma unroll
    for (int i = 0; i < 32; i += 8)
        tile[ty + i][tx] = W[(size_t)(k0 + ty + i) * N + n0 + tx];
    __syncthreads();
    #pragma unroll
    for (int i = 0; i < 32; i += 8) {
        float v = tile[tx][ty + i];
        __nv_bfloat16 h = __float2bfloat16(v);
        __nv_bfloat16 l = __float2bfloat16(v - __bfloat162float(h));
        size_t o = (size_t)(n0 + ty + i) * K + k0 + tx;
        th[o] = h;
        tl[o] = l;
    }
}

// ---------------- split-bf16 GEMM via mma.sync ----------------
constexpr int BK       = 32;
constexpr int PITCH    = 80;
constexpr int TILE_BYT = 128 * PITCH;
constexpr int STAGE_BYT = 4 * TILE_BYT;
constexpr int GEMM_SMEM = 2 * STAGE_BYT;     // 81920

template <bool SPLIT>
__global__ __launch_bounds__(256, 2)
void tc_gemm(const __nv_bfloat16* __restrict__ Ah, const __nv_bfloat16* __restrict__ Al,
             const __nv_bfloat16* __restrict__ Bh, const __nv_bfloat16* __restrict__ Bl,
             float* __restrict__ Cf, __nv_bfloat16* __restrict__ Ch,
             __nv_bfloat16* __restrict__ Cl, int Ncols, int K) {
    extern __shared__ __align__(128) char smem[];
    const uint32_t sbase = smem_u32(smem);
    const int tid  = threadIdx.x;
    const int wid  = tid >> 5, lane = tid & 31;
    const int wm   = wid & 1;
    const int wn   = wid >> 1;
    const int m0   = blockIdx.y * 128, n0 = blockIdx.x * 128;

    const uint32_t aoff = (uint32_t)(lane & 15) * PITCH + (uint32_t)(lane >> 4) * 16;
    const uint32_t boff = (uint32_t)((lane & 7) + ((lane >> 4) & 1) * 8) * PITCH +
                          (uint32_t)((lane >> 3) & 1) * 16;

    float acc[4][4][4];
    #pragma unroll
    for (int i = 0; i < 4; i++)
        #pragma unroll
        for (int j = 0; j < 4; j++)
            #pragma unroll
            for (int q = 0; q < 4; q++) acc[i][j][q] = 0.f;

    const int NS = K / BK;
    const int lr = tid >> 2;
    const int lc = tid & 3;

    auto load_stage = [&](int s, int b) {
        uint32_t base = sbase + (uint32_t)b * STAGE_BYT;
        const int k0 = s * BK;
        const __nv_bfloat16* srcs[4] = {Ah, Al, Bh, Bl};
        const int rows[4] = {m0, m0, n0, n0};
        #pragma unroll
        for (int t = 0; t < 4; t++) {
            uint32_t tb = base + (uint32_t)t * TILE_BYT;
            #pragma unroll
            for (int p = 0; p < 2; p++) {
                int r = lr + p * 64;
                cp16(tb + (uint32_t)r * PITCH + (uint32_t)lc * 16,
                     (const char*)(srcs[t] + (size_t)(rows[t] + r) * K + k0) + lc * 16);
            }
        }
        CP_COMMIT();
    };

    load_stage(0, 0);

    for (int i = 0; i < NS; ++i) {
        const int buf = i & 1;
        if (i + 1 < NS) { load_stage(i + 1, buf ^ 1); CP_WAIT(1); }
        else           { CP_WAIT(0); }
        __syncthreads();

        const uint32_t base = sbase + (uint32_t)buf * STAGE_BYT;
        const uint32_t aH = base, aL = base + TILE_BYT;
        const uint32_t bH = base + 2 * TILE_BYT, bL = base + 3 * TILE_BYT;
        const uint32_t arow = (uint32_t)(wm * 64) * PITCH;
        const uint32_t brow = (uint32_t)(wn * 32) * PITCH;

        #pragma unroll
        for (int kk = 0; kk < 2; ++kk) {
            const uint32_t kb = (uint32_t)kk * 32;
            uint32_t af[4][4], bf[4][2];

            #pragma unroll
            for (int mi = 0; mi < 4; mi++)
                ldm_x4(af[mi], aH + arow + (uint32_t)(mi * 16) * PITCH + kb + aoff);
            #pragma unroll
            for (int np = 0; np < 2; np++) {
                uint32_t t[4];
                ldm_x4(t, bH + brow + (uint32_t)(np * 16) * PITCH + kb + boff);
                bf[2 * np][0] = t[0]; bf[2 * np][1] = t[1];
                bf[2 * np + 1][0] = t[2]; bf[2 * np + 1][1] = t[3];
            }
            #pragma unroll
            for (int mi = 0; mi < 4; mi++)
                #pragma unroll
                for (int ni = 0; ni < 4; ni++)
                    mma16816(acc[mi][ni], af[mi], bf[ni][0], bf[ni][1]);

            #pragma unroll
            for (int np = 0; np < 2; np++) {
                uint32_t t[4];
                ldm_x4(t, bL + brow + (uint32_t)(np * 16) * PITCH + kb + boff);
                bf[2 * np][0] = t[0]; bf[2 * np][1] = t[1];
                bf[2 * np + 1][0] = t[2]; bf[2 * np + 1][1] = t[3];
            }
            #pragma unroll
            for (int mi = 0; mi < 4; mi++)
                #pragma unroll
                for (int ni = 0; ni < 4; ni++)
                    mma16816(acc[mi][ni], af[mi], bf[ni][0], bf[ni][1]);

            #pragma unroll
            for (int mi = 0; mi < 4; mi++)
                ldm_x4(af[mi], aL + arow + (uint32_t)(mi * 16) * PITCH + kb + aoff);
            #pragma unroll
            for (int np = 0; np < 2; np++) {
                uint32_t t[4];
                ldm_x4(t, bH + brow + (uint32_t)(np * 16) * PITCH + kb + boff);
                bf[2 * np][0] = t[0]; bf[2 * np][1] = t[1];
                bf[2 * np + 1][0] = t[2]; bf[2 * np + 1][1] = t[3];
            }
            #pragma unroll
            for (int mi = 0; mi < 4; mi++)
                #pragma unroll
                for (int ni = 0; ni < 4; ni++)
                    mma16816(acc[mi][ni], af[mi], bf[ni][0], bf[ni][1]);
        }
        __syncthreads();
    }

    const int rbase = m0 + wm * 64 + (lane >> 2);
    const int cbase = n0 + wn * 32 + (lane & 3) * 2;
    #pragma unroll
    for (int mi = 0; mi < 4; mi++) {
        #pragma unroll
        for (int ni = 0; ni < 4; ni++) {
            int row = rbase + mi * 16;
            int col = cbase + ni * 8;
            if (SPLIT) {
                #pragma unroll
                for (int half = 0; half < 2; half++) {
                    int rr = row + half * 8;
                    float v0 = acc[mi][ni][2 * half], v1 = acc[mi][ni][2 * half + 1];
                    __nv_bfloat16 h0 = __float2bfloat16(v0), h1 = __float2bfloat16(v1);
                    __nv_bfloat16 l0 = __float2bfloat16(v0 - __bfloat162float(h0));
                    __nv_bfloat16 l1 = __float2bfloat16(v1 - __bfloat162float(h1));
                    *(__nv_bfloat162*)&Ch[(size_t)rr * Ncols + col] = __halves2bfloat162(h0, h1);
                    *(__nv_bfloat162*)&Cl[(size_t)rr * Ncols + col] = __halves2bfloat162(l0, l1);
                }
            } else {
                *(float2*)&Cf[(size_t)row * Ncols + col] =
                    make_float2(acc[mi][ni][0], acc[mi][ni][1]);
                *(float2*)&Cf[(size_t)(row + 8) * Ncols + col] =
                    make_float2(acc[mi][ni][2], acc[mi][ni][3]);
            }
        }
    }
}

// ---------------- tensor-core causal GQA flash attention (split bf16) ----------------
// CTA: 128 q rows for one (b,h,qtile). 8 warps x 16 rows. K-tile 64 keys.
constexpr int APITCH  = 272;                  // 256B data + 16B pad per 128-bf16 row
constexpr int AT_TILE = 64 * APITCH;          // 17408 per K/V h/l tile
constexpr int AT_SMEM = 4 * AT_TILE;          // 69632

__global__ __launch_bounds__(256, 1)
void attn_mma(const __nv_bfloat16* __restrict__ Qh, const __nv_bfloat16* __restrict__ Ql,
              const __nv_bfloat16* __restrict__ Kh, const __nv_bfloat16* __restrict__ Kl,
              const __nv_bfloat16* __restrict__ Vh, const __nv_bfloat16* __restrict__ Vl,
              __nv_bfloat16* __restrict__ Yh, __nv_bfloat16* __restrict__ Yl) {
    extern __shared__ __align__(128) char smem[];
    const uint32_t sb = smem_u32(smem);
    const uint32_t KH = sb, KL = sb + AT_TILE, VH = sb + 2 * AT_TILE, VL = sb + 3 * AT_TILE;

    const int qi = blockIdx.x, h = blockIdx.y, b = blockIdx.z;
    const int kvh = h / GROUP;
    const int q0  = qi * 128;
    const int tid = threadIdx.x, wid = tid >> 5, lane = tid & 31;

    const uint32_t aoff = (uint32_t)(lane & 15) * APITCH + (uint32_t)(lane >> 4) * 16;
    const uint32_t boff = (uint32_t)((lane & 7) + ((lane >> 3) & 1) * 8) * APITCH +
                          (uint32_t)(lane >> 4) * 16;
    const float SCL2 = 0.127517408f;  // (1/sqrt(128)) * log2(e)

    // ---- stage Q tile (h into K-area, l into V-area), grab frags into regs ----
    {
        const __nv_bfloat16* gqh = Qh + ((size_t)(b * T_ + q0)) * C_ + h * HEADD;
        const __nv_bfloat16* gql = Ql + ((size_t)(b * T_ + q0)) * C_ + h * HEADD;
        #pragma unroll
        for (int i = 0; i < 8; i++) {
            int idx = tid + i * 256;                  // 0..2047
            int row = idx >> 4, ch = idx & 15;
            cp16(KH + (uint32_t)row * APITCH + (uint32_t)ch * 16,
                 (const char*)(gqh + (size_t)row * C_) + ch * 16);
            cp16(VH + (uint32_t)row * APITCH + (uint32_t)ch * 16,
                 (const char*)(gql + (size_t)row * C_) + ch * 16);
        }
        CP_COMMIT(); CP_WAIT(0);
        __syncthreads();
    }
    uint32_t qfh[8][4], qfl[8][4];
    #pragma unroll
    for (int kb = 0; kb < 8; kb++) {
        ldm_x4(qfh[kb], KH + (uint32_t)(wid * 16) * APITCH + (uint32_t)kb * 32 + aoff);
        ldm_x4(qfl[kb], VH + (uint32_t)(wid * 16) * APITCH + (uint32_t)kb * 32 + aoff);
    }
    __syncthreads();

    float o[16][4];
    #pragma unroll
    for (int i = 0; i < 16; i++)
        #pragma unroll
        for (int q = 0; q < 4; q++) o[i][q] = 0.f;
    float m0 = -1e30f, m1 = -1e30f, l0 = 0.f, l1 = 0.f;

    const int ntiles = 2 * qi + 2;

    auto load_K = [&](int j) {
        const size_t gb = ((size_t)(b * T_ + j * 64)) * KVC + kvh * HEADD;
        #pragma unroll
        for (int i = 0; i < 4; i++) {
            int idx = tid + i * 256;                  // 0..1023
            int row = idx >> 4, ch = idx & 15;
            uint32_t so = (uint32_t)row * APITCH + (uint32_t)ch * 16;
            cp16(KH + so, (const char*)(Kh + gb + (size_t)row * KVC) + ch * 16);
            cp16(KL + so, (const char*)(Kl + gb + (size_t)row * KVC) + ch * 16);
        }
        CP_COMMIT();
    };
    auto load_V = [&](int j) {
        const size_t gb = ((size_t)(b * T_ + j * 64)) * KVC + kvh * HEADD;
        #pragma unroll
        for (int i = 0; i < 4; i++) {
            int idx = tid + i * 256;
            int row = idx >> 4, ch = idx & 15;
            uint32_t so = (uint32_t)row * APITCH + (uint32_t)ch * 16;
            cp16(VH + so, (const char*)(Vh + gb + (size_t)row * KVC) + ch * 16);
            cp16(VL + so, (const char*)(Vl + gb + (size_t)row * KVC) + ch * 16);
        }
        CP_COMMIT();
    };

    load_K(0);
    load_V(0);
    CP_WAIT(1);          // K0 done, V0 in flight
    __syncthreads();

    const int row0 = q0 + wid * 16 + (lane >> 2);
    const int row1 = row0 + 8;

    for (int j = 0; j < ntiles; j++) {
        // ---------- scores S = (Qh+Ql)(Kh+Kl)^T ----------
        float s[8][4];
        #pragma unroll
        for (int nb = 0; nb < 8; nb++)
            #pragma unroll
            for (int q = 0; q < 4; q++) s[nb][q] = 0.f;

        #pragma unroll
        for (int kb = 0; kb < 8; kb++) {
            uint32_t kf[4][4];
            #pragma unroll
            for (int kg = 0; kg < 4; kg++)
                ldm_x4(kf[kg], KH + (uint32_t)(kg * 16) * APITCH + (uint32_t)kb * 32 + boff);
            #pragma unroll
            for (int nb = 0; nb < 8; nb++)
                mma16816(s[nb], qfh[kb], kf[nb >> 1][nb & 1], kf[nb >> 1][(nb & 1) + 2]);
            #pragma unroll
            for (int nb = 0; nb < 8; nb++)
                mma16816(s[nb], qfl[kb], kf[nb >> 1][nb & 1], kf[nb >> 1][(nb & 1) + 2]);
            #pragma unroll
            for (int kg = 0; kg < 4; kg++)
                ldm_x4(kf[kg], KL + (uint32_t)(kg * 16) * APITCH + (uint32_t)kb * 32 + boff);
            #pragma unroll
            for (int nb = 0; nb < 8; nb++)
                mma16816(s[nb], qfh[kb], kf[nb >> 1][nb & 1], kf[nb >> 1][(nb & 1) + 2]);
        }
        __syncthreads();                     // all warps done reading K[j]
        if (j + 1 < ntiles) { load_K(j + 1); CP_WAIT(1); }  // V[j] done, K[j+1] in flight
        else                { CP_WAIT(0); }
        __syncthreads();

        // ---------- online softmax ----------
        const int k0 = j * 64;
        const bool masked = (j >= 2 * qi);
        float mt0 = -1e30f, mt1 = -1e30f;
        #pragma unroll
        for (int nb = 0; nb < 8; nb++) {
            #pragma unroll
            for (int q = 0; q < 4; q++) {
                float v = s[nb][q] * SCL2;
                if (masked) {
                    int key = k0 + nb * 8 + (lane & 3) * 2 + (q & 1);
                    int qr  = (q < 2) ? row0 : row1;
                    if (key > qr) v = -1e30f;
                }
                s[nb][q] = v;
                if (q < 2) mt0 = fmaxf(mt0, v); else mt1 = fmaxf(mt1, v);
            }
        }
        mt0 = fmaxf(mt0, __shfl_xor_sync(0xffffffffu, mt0, 1));
        mt0 = fmaxf(mt0, __shfl_xor_sync(0xffffffffu, mt0, 2));
        mt1 = fmaxf(mt1, __shfl_xor_sync(0xffffffffu, mt1, 1));
        mt1 = fmaxf(mt1, __shfl_xor_sync(0xffffffffu, mt1, 2));

        float m0n = fmaxf(m0, mt0), m1n = fmaxf(m1, mt1);
        float c0 = fast_ex2(m0 - m0n), c1 = fast_ex2(m1 - m1n);
        m0 = m0n; m1 = m1n;

        float lt0 = 0.f, lt1 = 0.f;
        #pragma unroll
        for (int nb = 0; nb < 8; nb++) {
            #pragma unroll
            for (int q = 0; q < 4; q++) {
                float p = fast_ex2(s[nb][q] - ((q < 2) ? m0 : m1));
                s[nb][q] = p;
                if (q < 2) lt0 += p; else lt1 += p;
            }
        }
        l0 = l0 * c0 + lt0;
        l1 = l1 * c1 + lt1;
        #pragma unroll
        for (int ob = 0; ob < 16; ob++) {
            o[ob][0] *= c0; o[ob][1] *= c0;
            o[ob][2] *= c1; o[ob][3] *= c1;
        }

        // ---------- PV: O += (Ph+Pl)(Vh+Vl) ----------
        #pragma unroll
        for (int kb2 = 0; kb2 < 4; kb2++) {
            uint32_t pah[4], pal[4];
            #pragma unroll
            for (int half = 0; half < 2; half++) {     // blocks 2*kb2, 2*kb2+1
                int nb = 2 * kb2 + half;
                float p0 = s[nb][0], p1 = s[nb][1], p2 = s[nb][2], p3 = s[nb][3];
                uint32_t h01 = pack_bf16(p0, p1), h23 = pack_bf16(p2, p3);
                __nv_bfloat162 hv01 = *(__nv_bfloat162*)&h01;
                __nv_bfloat162 hv23 = *(__nv_bfloat162*)&h23;
                uint32_t lo01 = pack_bf16(p0 - __bfloat162float(__low2bfloat16(hv01)),
                                          p1 - __bfloat162float(__high2bfloat16(hv01)));
                uint32_t lo23 = pack_bf16(p2 - __bfloat162float(__low2bfloat16(hv23)),
                                          p3 - __bfloat162float(__high2bfloat16(hv23)));
                pah[2 * half] = h01; pah[2 * half + 1] = h23;
                pal[2 * half] = lo01; pal[2 * half + 1] = lo23;
            }
            #pragma unroll
            for (int dg = 0; dg < 8; dg++) {
                uint32_t vf[4];
                ldm_x4_t(vf, VH + (uint32_t)(kb2 * 16) * APITCH + (uint32_t)dg * 32 + boff);
                mma16816(o[2 * dg],     pah, vf[0], vf[1]);
                mma16816(o[2 * dg + 1], pah, vf[2], vf[3]);
                mma16816(o[2 * dg],     pal, vf[0], vf[1]);
                mma16816(o[2 * dg + 1], pal, vf[2], vf[3]);
                ldm_x4_t(vf, VL + (uint32_t)(kb2 * 16) * APITCH + (uint32_t)dg * 32 + boff);
                mma16816(o[2 * dg],     pah, vf[0], vf[1]);
                mma16816(o[2 * dg + 1], pah, vf[2], vf[3]);
            }
        }
        __syncthreads();                     // all warps done reading V[j]
        if (j + 1 < ntiles) { load_V(j + 1); CP_WAIT(1); }  // K[j+1] done, V[j+1] in flight
        else                { CP_WAIT(0); }
        __syncthreads();
    }

    // ---------- epilogue: normalize, split, write ----------
    l0 += __shfl_xor_sync(0xffffffffu, l0, 1);
    l0 += __shfl_xor_sync(0xffffffffu, l0, 2);
    l1 += __shfl_xor_sync(0xffffffffu, l1, 1);
    l1 += __shfl_xor_sync(0xffffffffu, l1, 2);
    const float i0 = 1.f / l0, i1 = 1.f / l1;

    #pragma unroll
    for (int ob = 0; ob < 16; ob++) {
        const int col = h * HEADD + ob * 8 + (lane & 3) * 2;
        #pragma unroll
        for (int half = 0; half < 2; half++) {
            const int rr = (half == 0) ? row0 : row1;
            const float sc = (half == 0) ? i0 : i1;
            float y0 = o[ob][2 * half] * sc, y1 = o[ob][2 * half + 1] * sc;
            __nv_bfloat16 h0 = __float2bfloat16(y0), h1 = __float2bfloat16(y1);
            __nv_bfloat16 e0 = __float2bfloat16(y0 - __bfloat162float(h0));
            __nv_bfloat16 e1 = __float2bfloat16(y1 - __bfloat162float(h1));
            size_t off = (size_t)(b * T_ + rr) * C_ + col;
            *(__nv_bfloat162*)&Yh[off] = __halves2bfloat162(h0, h1);
            *(__nv_bfloat162*)&Yl[off] = __halves2bfloat162(e0, e1);
        }
    }
}

// ---------------- launch ----------------
extern "C" void kernel_launch(void* const* d_in, const int* in_sizes, int n_in,
                              void* d_out, int out_size) {
    const float* x  = (const float*)d_in[0];
    const float* Wq = (const float*)d_in[1];
    const float* Wk = (const float*)d_in[2];
    const float* Wv = (const float*)d_in[3];
    const float* Wo = (const float*)d_in[4];
    float* out = (float*)d_out;

    __nv_bfloat16 *xh, *xl, *qh, *ql, *kh, *kl, *vh, *vl, *yh, *yl;
    __nv_bfloat16 *wqh, *wql, *wkh, *wkl, *wvh, *wvl, *woh, *wol;
    cudaGetSymbolAddress((void**)&xh, g_xh);   cudaGetSymbolAddress((void**)&xl, g_xl);
    cudaGetSymbolAddress((void**)&qh, g_qh);   cudaGetSymbolAddress((void**)&ql, g_ql);
    cudaGetSymbolAddress((void**)&kh, g_kh);   cudaGetSymbolAddress((void**)&kl, g_kl);
    cudaGetSymbolAddress((void**)&vh, g_vh);   cudaGetSymbolAddress((void**)&vl, g_vl);
    cudaGetSymbolAddress((void**)&yh, g_yh);   cudaGetSymbolAddress((void**)&yl, g_yl);
    cudaGetSymbolAddress((void**)&wqh, g_wqh); cudaGetSymbolAddress((void**)&wql, g_wql);
    cudaGetSymbolAddress((void**)&wkh, g_wkh); cudaGetSymbolAddress((void**)&wkl, g_wkl);
    cudaGetSymbolAddress((void**)&wvh, g_wvh); cudaGetSymbolAddress((void**)&wvl, g_wvl);
    cudaGetSymbolAddress((void**)&woh, g_woh); cudaGetSymbolAddress((void**)&wol, g_wol);

    cudaFuncSetAttribute(tc_gemm<true>,  cudaFuncAttributeMaxDynamicSharedMemorySize, GEMM_SMEM);
    cudaFuncSetAttribute(tc_gemm<false>, cudaFuncAttributeMaxDynamicSharedMemorySize, GEMM_SMEM);
    cudaFuncSetAttribute(attn_mma, cudaFuncAttributeMaxDynamicSharedMemorySize, AT_SMEM);

    // 1) split inputs / weights
    {
        int n4 = M_ * C_ / 4;
        split_kernel<<<(n4 + 255) / 256, 256>>>(x, xh, xl, n4);
        dim3 tb(32, 8);
        split_transpose_kernel<<<dim3(C_ / 32,  C_ / 32), tb>>>(Wq, wqh, wql, C_, C_);
        split_transpose_kernel<<<dim3(KVC / 32, C_ / 32), tb>>>(Wk, wkh, wkl, C_, KVC);
        split_transpose_kernel<<<dim3(KVC / 32, C_ / 32), tb>>>(Wv, wvh, wvl, C_, KVC);
        split_transpose_kernel<<<dim3(C_ / 32,  C_ / 32), tb>>>(Wo, woh, wol, C_, C_);
    }

    // 2) projections -> split bf16 outputs
    dim3 blk(256);
    tc_gemm<true><<<dim3(C_ / 128,  M_ / 128), blk, GEMM_SMEM>>>(xh, xl, wqh, wql, nullptr, qh, ql, C_,  C_);
    tc_gemm<true><<<dim3(KVC / 128, M_ / 128), blk, GEMM_SMEM>>>(xh, xl, wkh, wkl, nullptr, kh, kl, KVC, C_);
    tc_gemm<true><<<dim3(KVC / 128, M_ / 128), blk, GEMM_SMEM>>>(xh, xl, wvh, wvl, nullptr, vh, vl, KVC, C_);

    // 3) tensor-core attention -> split bf16 Y
    attn_mma<<<dim3(T_ / 128, NH, B_), blk, AT_SMEM>>>(qh, ql, kh, kl, vh, vl, yh, yl);

    // 4) output projection -> fp32 out
    tc_gemm<false><<<dim3(C_ / 128, M_ / 128), blk, GEMM_SMEM>>>(yh, yl, woh, wol, out, nullptr, nullptr, C_, C_);
}

// round 7
// speedup vs baseline: 13.9943x; 1.5684x over previous
#include <cuda_runtime.h>
#include <cuda_fp16.h>
#include <math_constants.h>
#include <cstdint>

// ---------------- problem constants ----------------
constexpr int B_    = 2;
constexpr int T_    = 2048;
constexpr int C_    = 2048;
constexpr int NH    = 16;
constexpr int NKV   = 4;
constexpr int HEADD = 128;
constexpr int GROUP = NH / NKV;     // 4
constexpr int KVC   = NKV * HEADD;  // 512
constexpr int M_    = B_ * T_;      // 4096
constexpr int NQKV  = C_ + 2 * KVC; // 3072

// ---------------- scratch ----------------
__device__ __half g_xh[(size_t)M_ * C_],  g_xl[(size_t)M_ * C_];
__device__ __half g_qh[(size_t)M_ * C_],  g_ql[(size_t)M_ * C_];
__device__ __half g_kh[(size_t)M_ * KVC];
__device__ __half g_vh[(size_t)M_ * KVC];
__device__ __half g_yh[(size_t)M_ * C_],  g_yl[(size_t)M_ * C_];
__device__ __half g_wh[(size_t)NQKV * C_];    // [n][k] k-major, Wq|Wk|Wv hi
__device__ __half g_woh[(size_t)C_ * C_];     // Wo hi, k-major

// ---------------- PTX helpers ----------------
__device__ __forceinline__ uint32_t smem_u32(const void* p) {
    uint32_t a;
    asm("{ .reg .u64 t; cvta.to.shared.u64 t, %1; cvt.u32.u64 %0, t; }" : "=r"(a) : "l"(p));
    return a;
}
#define CP_COMMIT()   asm volatile("cp.async.commit_group;" ::: "memory")
#define CP_WAIT(n)    asm volatile("cp.async.wait_group %0;" :: "n"(n) : "memory")
__device__ __forceinline__ void cp16(uint32_t dst, const void* src) {
    asm volatile("cp.async.cg.shared.global [%0], [%1], 16;" :: "r"(dst), "l"(src));
}
__device__ __forceinline__ void ldm_x4(uint32_t* r, uint32_t addr) {
    asm volatile("ldmatrix.sync.aligned.m8n8.x4.shared.b16 {%0,%1,%2,%3}, [%4];"
        : "=r"(r[0]), "=r"(r[1]), "=r"(r[2]), "=r"(r[3]) : "r"(addr));
}
__device__ __forceinline__ void ldm_x4_t(uint32_t* r, uint32_t addr) {
    asm volatile("ldmatrix.sync.aligned.m8n8.x4.trans.shared.b16 {%0,%1,%2,%3}, [%4];"
        : "=r"(r[0]), "=r"(r[1]), "=r"(r[2]), "=r"(r[3]) : "r"(addr));
}
__device__ __forceinline__ void mma16816(float* d, const uint32_t* a, uint32_t b0, uint32_t b1) {
    asm volatile("mma.sync.aligned.m16n8k16.row.col.f32.f16.f16.f32 "
        "{%0,%1,%2,%3}, {%4,%5,%6,%7}, {%8,%9}, {%0,%1,%2,%3};"
        : "+f"(d[0]), "+f"(d[1]), "+f"(d[2]), "+f"(d[3])
        : "r"(a[0]), "r"(a[1]), "r"(a[2]), "r"(a[3]), "r"(b0), "r"(b1));
}
__device__ __forceinline__ float fast_ex2(float x) {
    float y;
    asm("ex2.approx.f32 %0, %1;" : "=f"(y) : "f"(x));
    return y;
}
__device__ __forceinline__ uint32_t pack_h16(float a, float b) {
    __half2 v = __floats2half2_rn(a, b);
    return *(uint32_t*)&v;
}

// ---------------- conversion kernels ----------------
__global__ void split_kernel(const float* __restrict__ in, __half* __restrict__ hi,
                             __half* __restrict__ lo, int n4) {
    int i = blockIdx.x * 256 + threadIdx.x;
    if (i >= n4) return;
    float4 v = ((const float4*)in)[i];
    float vs[4] = {v.x, v.y, v.z, v.w};
    __half h[4], l[4];
    #pragma unroll
    for (int j = 0; j < 4; j++) {
        h[j] = __float2half_rn(vs[j]);
        l[j] = __float2half_rn(vs[j] - __half2float(h[j]));
    }
    ((__half2*)hi)[2 * i]     = __halves2half2(h[0], h[1]);
    ((__half2*)hi)[2 * i + 1] = __halves2half2(h[2], h[3]);
    ((__half2*)lo)[2 * i]     = __halves2half2(l[0], l[1]);
    ((__half2*)lo)[2 * i + 1] = __halves2half2(l[2], l[3]);
}

// W (K x N fp32, row-major) -> th[(rowoff+n)][k] fp16 hi, k-major
__global__ void transpose_h_kernel(const float* __restrict__ W, __half* __restrict__ th,
                                   int K, int N, int rowoff) {
    __shared__ float tile[32][33];
    int n0 = blockIdx.x * 32, k0 = blockIdx.y * 32;
    int tx = threadIdx.x, ty = threadIdx.y;  // 32 x 8
    #pragma unroll
    for (int i = 0; i < 32; i += 8)
        tile[ty + i][tx] = W[(size_t)(k0 + ty + i) * N + n0 + tx];
    __syncthreads();
    #pragma unroll
    for (int i = 0; i < 32; i += 8)
        th[(size_t)(rowoff + n0 + ty + i) * K + k0 + tx] = __float2half_rn(tile[tx][ty + i]);
}

// ---------------- 2-term fp16 GEMM via mma.sync ----------------
// C = (Ah+Al) * Bh^T; A [M][K] row-major hi/lo, Bh [N][K] k-major.
constexpr int BK        = 32;
constexpr int PITCH     = 80;
constexpr int TILE_BYT  = 128 * PITCH;        // 10240
constexpr int STAGE_BYT = 3 * TILE_BYT;       // Ah, Al, Bh = 30720
constexpr int GEMM_SMEM = 2 * STAGE_BYT;      // 61440

// MODE 0: write fp32 Cf (Ncols = C_).  MODE 1: fused QKV epilogue.
template <int MODE>
__global__ __launch_bounds__(256, 2)
void tc_gemm(const __half* __restrict__ Ah, const __half* __restrict__ Al,
             const __half* __restrict__ Bh, float* __restrict__ Cf,
             __half* __restrict__ Qh, __half* __restrict__ Ql,
             __half* __restrict__ Kh, __half* __restrict__ Vh, int K) {
    extern __shared__ __align__(128) char smem[];
    const uint32_t sbase = smem_u32(smem);
    const int tid  = threadIdx.x;
    const int wid  = tid >> 5, lane = tid & 31;
    const int wm   = wid & 1;
    const int wn   = wid >> 1;
    const int m0   = blockIdx.y * 128, n0 = blockIdx.x * 128;

    const uint32_t aoff = (uint32_t)(lane & 15) * PITCH + (uint32_t)(lane >> 4) * 16;
    const uint32_t boff = (uint32_t)((lane & 7) + ((lane >> 4) & 1) * 8) * PITCH +
                          (uint32_t)((lane >> 3) & 1) * 16;

    float acc[4][4][4];
    #pragma unroll
    for (int i = 0; i < 4; i++)
        #pragma unroll
        for (int j = 0; j < 4; j++)
            #pragma unroll
            for (int q = 0; q < 4; q++) acc[i][j][q] = 0.f;

    const int NS = K / BK;
    const int lr = tid >> 2;
    const int lc = tid & 3;

    auto load_stage = [&](int s, int b) {
        uint32_t base = sbase + (uint32_t)b * STAGE_BYT;
        const int k0 = s * BK;
        const __half* srcs[3] = {Ah, Al, Bh};
        const int rows[3] = {m0, m0, n0};
        #pragma unroll
        for (int t = 0; t < 3; t++) {
            uint32_t tb = base + (uint32_t)t * TILE_BYT;
            #pragma unroll
            for (int p = 0; p < 2; p++) {
                int r = lr + p * 64;
                cp16(tb + (uint32_t)r * PITCH + (uint32_t)lc * 16,
                     (const char*)(srcs[t] + (size_t)(rows[t] + r) * K + k0) + lc * 16);
            }
        }
        CP_COMMIT();
    };

    load_stage(0, 0);

    for (int i = 0; i < NS; ++i) {
        const int buf = i & 1;
        if (i + 1 < NS) { load_stage(i + 1, buf ^ 1); CP_WAIT(1); }
        else           { CP_WAIT(0); }
        __syncthreads();

        const uint32_t base = sbase + (uint32_t)buf * STAGE_BYT;
        const uint32_t aH = base, aL = base + TILE_BYT, bH = base + 2 * TILE_BYT;
        const uint32_t arow = (uint32_t)(wm * 64) * PITCH;
        const uint32_t brow = (uint32_t)(wn * 32) * PITCH;

        #pragma unroll
        for (int kk = 0; kk < 2; ++kk) {
            const uint32_t kb = (uint32_t)kk * 32;
            uint32_t ah[4][4], al[4][4], bf[4][2];

            #pragma unroll
            for (int mi = 0; mi < 4; mi++)
                ldm_x4(ah[mi], aH + arow + (uint32_t)(mi * 16) * PITCH + kb + aoff);
            #pragma unroll
            for (int mi = 0; mi < 4; mi++)
                ldm_x4(al[mi], aL + arow + (uint32_t)(mi * 16) * PITCH + kb + aoff);
            #pragma unroll
            for (int np = 0; np < 2; np++) {
                uint32_t t[4];
                ldm_x4(t, bH + brow + (uint32_t)(np * 16) * PITCH + kb + boff);
                bf[2 * np][0] = t[0]; bf[2 * np][1] = t[1];
                bf[2 * np + 1][0] = t[2]; bf[2 * np + 1][1] = t[3];
            }
            #pragma unroll
            for (int mi = 0; mi < 4; mi++)
                #pragma unroll
                for (int ni = 0; ni < 4; ni++) {
                    mma16816(acc[mi][ni], ah[mi], bf[ni][0], bf[ni][1]);
                    mma16816(acc[mi][ni], al[mi], bf[ni][0], bf[ni][1]);
                }
        }
        __syncthreads();
    }

    const int rbase = m0 + wm * 64 + (lane >> 2);
    const int cbase = n0 + wn * 32 + (lane & 3) * 2;
    #pragma unroll
    for (int mi = 0; mi < 4; mi++) {
        #pragma unroll
        for (int ni = 0; ni < 4; ni++) {
            int col = cbase + ni * 8;
            #pragma unroll
            for (int half = 0; half < 2; half++) {
                int row = rbase + mi * 16 + half * 8;
                float v0 = acc[mi][ni][2 * half], v1 = acc[mi][ni][2 * half + 1];
                if (MODE == 0) {
                    *(float2*)&Cf[(size_t)row * C_ + col] = make_float2(v0, v1);
                } else {
                    if (col < C_) {          // Q: split hi/lo
                        __half h0 = __float2half_rn(v0), h1 = __float2half_rn(v1);
                        __half l0 = __float2half_rn(v0 - __half2float(h0));
                        __half l1 = __float2half_rn(v1 - __half2float(h1));
                        *(__half2*)&Qh[(size_t)row * C_ + col] = __halves2half2(h0, h1);
                        *(__half2*)&Ql[(size_t)row * C_ + col] = __halves2half2(l0, l1);
                    } else if (col < C_ + KVC) {  // K: hi only
                        *(__half2*)&Kh[(size_t)row * KVC + (col - C_)] =
                            __floats2half2_rn(v0, v1);
                    } else {                 // V: hi only
                        *(__half2*)&Vh[(size_t)row * KVC + (col - C_ - KVC)] =
                            __floats2half2_rn(v0, v1);
                    }
                }
            }
        }
    }
}

// ---------------- tensor-core causal GQA flash attention (fp16) ----------------
// CTA: 128 q rows. 8 warps x 16 rows. K-tile 64 keys. S=(Qh+Ql)Kh, O=Ph*Vh.
constexpr int APITCH  = 272;
constexpr int AT_TILE = 64 * APITCH;          // 17408
constexpr int AT_SMEM = 2 * AT_TILE;          // 34816 (KH | VH; Q staged across both)

__global__ __launch_bounds__(256, 1)
void attn_mma(const __half* __restrict__ Qh, const __half* __restrict__ Ql,
              const __half* __restrict__ Kh, const __half* __restrict__ Vh,
              __half* __restrict__ Yh, __half* __restrict__ Yl) {
    extern __shared__ __align__(128) char smem[];
    const uint32_t sb = smem_u32(smem);
    const uint32_t KH = sb, VH = sb + AT_TILE;

    const int qi = gridDim.x - 1 - blockIdx.x;     // heavy CTAs first
    const int h = blockIdx.y, b = blockIdx.z;
    const int kvh = h / GROUP;
    const int q0  = qi * 128;
    const int tid = threadIdx.x, wid = tid >> 5, lane = tid & 31;

    const uint32_t aoff = (uint32_t)(lane & 15) * APITCH + (uint32_t)(lane >> 4) * 16;
    const uint32_t boff = (uint32_t)((lane & 7) + ((lane >> 3) & 1) * 8) * APITCH +
                          (uint32_t)(lane >> 4) * 16;
    const float SCL2 = 0.127517408f;  // (1/sqrt(128)) * log2(e)

    // ---- stage Q hi then lo across KH+VH area, grab frags ----
    uint32_t qfh[8][4], qfl[8][4];
    {
        const __half* gq[2] = {Qh + ((size_t)(b * T_ + q0)) * C_ + h * HEADD,
                               Ql + ((size_t)(b * T_ + q0)) * C_ + h * HEADD};
        #pragma unroll
        for (int pass = 0; pass < 2; pass++) {
            #pragma unroll
            for (int i = 0; i < 8; i++) {
                int idx = tid + i * 256;              // 0..2047
                int row = idx >> 4, ch = idx & 15;
                cp16(KH + (uint32_t)row * APITCH + (uint32_t)ch * 16,
                     (const char*)(gq[pass] + (size_t)row * C_) + ch * 16);
            }
            CP_COMMIT(); CP_WAIT(0);
            __syncthreads();
            #pragma unroll
            for (int kb = 0; kb < 8; kb++) {
                uint32_t* dst = (pass == 0) ? qfh[kb] : qfl[kb];
                ldm_x4(dst, KH + (uint32_t)(wid * 16) * APITCH + (uint32_t)kb * 32 + aoff);
            }
            __syncthreads();
        }
    }

    float o[16][4];
    #pragma unroll
    for (int i = 0; i < 16; i++)
        #pragma unroll
        for (int q = 0; q < 4; q++) o[i][q] = 0.f;
    float m0 = -1e30f, m1 = -1e30f, l0 = 0.f, l1 = 0.f;

    const int ntiles = 2 * qi + 2;

    auto load_K = [&](int j) {
        const size_t gb = ((size_t)(b * T_ + j * 64)) * KVC + kvh * HEADD;
        #pragma unroll
        for (int i = 0; i < 4; i++) {
            int idx = tid + i * 256;                  // 0..1023
            int row = idx >> 4, ch = idx & 15;
            cp16(KH + (uint32_t)row * APITCH + (uint32_t)ch * 16,
                 (const char*)(Kh + gb + (size_t)row * KVC) + ch * 16);
        }
        CP_COMMIT();
    };
    auto load_V = [&](int j) {
        const size_t gb = ((size_t)(b * T_ + j * 64)) * KVC + kvh * HEADD;
        #pragma unroll
        for (int i = 0; i < 4; i++) {
            int idx = tid + i * 256;
            int row = idx >> 4, ch = idx & 15;
            cp16(VH + (uint32_t)row * APITCH + (uint32_t)ch * 16,
                 (const char*)(Vh + gb + (size_t)row * KVC) + ch * 16);
        }
        CP_COMMIT();
    };

    load_K(0);
    load_V(0);
    CP_WAIT(1);          // K0 done, V0 in flight
    __syncthreads();

    const int row0 = q0 + wid * 16 + (lane >> 2);
    const int row1 = row0 + 8;

    for (int j = 0; j < ntiles; j++) {
        // ---------- scores S = (Qh+Ql) Kh^T ----------
        float s[8][4];
        #pragma unroll
        for (int nb = 0; nb < 8; nb++)
            #pragma unroll
            for (int q = 0; q < 4; q++) s[nb][q] = 0.f;

        #pragma unroll
        for (int kb = 0; kb < 8; kb++) {
            uint32_t kf[4][4];
            #pragma unroll
            for (int kg = 0; kg < 4; kg++)
                ldm_x4(kf[kg], KH + (uint32_t)(kg * 16) * APITCH + (uint32_t)kb * 32 + boff);
            #pragma unroll
            for (int nb = 0; nb < 8; nb++) {
                mma16816(s[nb], qfh[kb], kf[nb >> 1][nb & 1], kf[nb >> 1][(nb & 1) + 2]);
                mma16816(s[nb], qfl[kb], kf[nb >> 1][nb & 1], kf[nb >> 1][(nb & 1) + 2]);
            }
        }
        __syncthreads();                     // all warps done reading K[j]
        if (j + 1 < ntiles) { load_K(j + 1); CP_WAIT(1); }  // V[j] done, K[j+1] in flight
        else                { CP_WAIT(0); }
        __syncthreads();

        // ---------- online softmax ----------
        const int k0 = j * 64;
        const bool masked = (j >= 2 * qi);
        float mt0 = -1e30f, mt1 = -1e30f;
        #pragma unroll
        for (int nb = 0; nb < 8; nb++) {
            #pragma unroll
            for (int q = 0; q < 4; q++) {
                float v = s[nb][q] * SCL2;
                if (masked) {
                    int key = k0 + nb * 8 + (lane & 3) * 2 + (q & 1);
                    int qr  = (q < 2) ? row0 : row1;
                    if (key > qr) v = -1e30f;
                }
                s[nb][q] = v;
                if (q < 2) mt0 = fmaxf(mt0, v); else mt1 = fmaxf(mt1, v);
            }
        }
        mt0 = fmaxf(mt0, __shfl_xor_sync(0xffffffffu, mt0, 1));
        mt0 = fmaxf(mt0, __shfl_xor_sync(0xffffffffu, mt0, 2));
        mt1 = fmaxf(mt1, __shfl_xor_sync(0xffffffffu, mt1, 1));
        mt1 = fmaxf(mt1, __shfl_xor_sync(0xffffffffu, mt1, 2));

        float m0n = fmaxf(m0, mt0), m1n = fmaxf(m1, mt1);
        float c0 = fast_ex2(m0 - m0n), c1 = fast_ex2(m1 - m1n);
        m0 = m0n; m1 = m1n;

        float lt0 = 0.f, lt1 = 0.f;
        #pragma unroll
        for (int nb = 0; nb < 8; nb++) {
            #pragma unroll
            for (int q = 0; q < 4; q++) {
                float p = fast_ex2(s[nb][q] - ((q < 2) ? m0 : m1));
                s[nb][q] = p;
                if (q < 2) lt0 += p; else lt1 += p;
            }
        }
        l0 = l0 * c0 + lt0;
        l1 = l1 * c1 + lt1;
        #pragma unroll
        for (int ob = 0; ob < 16; ob++) {
            o[ob][0] *= c0; o[ob][1] *= c0;
            o[ob][2] *= c1; o[ob][3] *= c1;
        }

        // ---------- PV: O += Ph * Vh ----------
        #pragma unroll
        for (int kb2 = 0; kb2 < 4; kb2++) {
            uint32_t pah[4];
            #pragma unroll
            for (int half = 0; half < 2; half++) {
                int nb = 2 * kb2 + half;
                pah[2 * half]     = pack_h16(s[nb][0], s[nb][1]);
                pah[2 * half + 1] = pack_h16(s[nb][2], s[nb][3]);
            }
            #pragma unroll
            for (int dg = 0; dg < 8; dg++) {
                uint32_t vf[4];
                ldm_x4_t(vf, VH + (uint32_t)(kb2 * 16) * APITCH + (uint32_t)dg * 32 + boff);
                mma16816(o[2 * dg],     pah, vf[0], vf[1]);
                mma16816(o[2 * dg + 1], pah, vf[2], vf[3]);
            }
        }
        __syncthreads();                     // all warps done reading V[j]
        if (j + 1 < ntiles) { load_V(j + 1); CP_WAIT(1); }  // K[j+1] done, V[j+1] in flight
        else                { CP_WAIT(0); }
        __syncthreads();
    }

    // ---------- epilogue: normalize, split fp16 hi/lo, write ----------
    l0 += __shfl_xor_sync(0xffffffffu, l0, 1);
    l0 += __shfl_xor_sync(0xffffffffu, l0, 2);
    l1 += __shfl_xor_sync(0xffffffffu, l1, 1);
    l1 += __shfl_xor_sync(0xffffffffu, l1, 2);
    const float i0 = 1.f / l0, i1 = 1.f / l1;

    #pragma unroll
    for (int ob = 0; ob < 16; ob++) {
        const int col = h * HEADD + ob * 8 + (lane & 3) * 2;
        #pragma unroll
        for (int half = 0; half < 2; half++) {
            const int rr = (half == 0) ? row0 : row1;
            const float sc = (half == 0) ? i0 : i1;
            float y0 = o[ob][2 * half] * sc, y1 = o[ob][2 * half + 1] * sc;
            __half h0 = __float2half_rn(y0), h1 = __float2half_rn(y1);
            __half e0 = __float2half_rn(y0 - __half2float(h0));
            __half e1 = __float2half_rn(y1 - __half2float(h1));
            size_t off = (size_t)(b * T_ + rr) * C_ + col;
            *(__half2*)&Yh[off] = __halves2half2(h0, h1);
            *(__half2*)&Yl[off] = __halves2half2(e0, e1);
        }
    }
}

// ---------------- launch ----------------
extern "C" void kernel_launch(void* const* d_in, const int* in_sizes, int n_in,
                              void* d_out, int out_size) {
    const float* x  = (const float*)d_in[0];
    const float* Wq = (const float*)d_in[1];
    const float* Wk = (const float*)d_in[2];
    const float* Wv = (const float*)d_in[3];
    const float* Wo = (const float*)d_in[4];
    float* out = (float*)d_out;

    __half *xh, *xl, *qh, *ql, *kh, *vh, *yh, *yl, *wh, *woh;
    cudaGetSymbolAddress((void**)&xh, g_xh);   cudaGetSymbolAddress((void**)&xl, g_xl);
    cudaGetSymbolAddress((void**)&qh, g_qh);   cudaGetSymbolAddress((void**)&ql, g_ql);
    cudaGetSymbolAddress((void**)&kh, g_kh);   cudaGetSymbolAddress((void**)&vh, g_vh);
    cudaGetSymbolAddress((void**)&yh, g_yh);   cudaGetSymbolAddress((void**)&yl, g_yl);
    cudaGetSymbolAddress((void**)&wh, g_wh);   cudaGetSymbolAddress((void**)&woh, g_woh);

    cudaFuncSetAttribute(tc_gemm<0>, cudaFuncAttributeMaxDynamicSharedMemorySize, GEMM_SMEM);
    cudaFuncSetAttribute(tc_gemm<1>, cudaFuncAttributeMaxDynamicSharedMemorySize, GEMM_SMEM);

    // 1) conversions
    {
        int n4 = M_ * C_ / 4;
        split_kernel<<<(n4 + 255) / 256, 256>>>(x, xh, xl, n4);
        dim3 tb(32, 8);
        transpose_h_kernel<<<dim3(C_ / 32,  C_ / 32), tb>>>(Wq, wh,  C_, C_,  0);
        transpose_h_kernel<<<dim3(KVC / 32, C_ / 32), tb>>>(Wk, wh,  C_, KVC, C_);
        transpose_h_kernel<<<dim3(KVC / 32, C_ / 32), tb>>>(Wv, wh,  C_, KVC, C_ + KVC);
        transpose_h_kernel<<<dim3(C_ / 32,  C_ / 32), tb>>>(Wo, woh, C_, C_,  0);
    }

    dim3 blk(256);
    // 2) fused QKV projection
    tc_gemm<1><<<dim3(NQKV / 128, M_ / 128), blk, GEMM_SMEM>>>(
        xh, xl, wh, nullptr, qh, ql, kh, vh, C_);

    // 3) attention
    attn_mma<<<dim3(T_ / 128, NH, B_), blk, AT_SMEM>>>(qh, ql, kh, vh, yh, yl);

    // 4) output projection
    tc_gemm<0><<<dim3(C_ / 128, M_ / 128), blk, GEMM_SMEM>>>(
        yh, yl, woh, out, nullptr, nullptr, nullptr, nullptr, C_);
}

// round 8
// speedup vs baseline: 14.2490x; 1.0182x over previous
#include <cuda_runtime.h>
#include <cuda_fp16.h>
#include <math_constants.h>
#include <cstdint>

// ---------------- problem constants ----------------
constexpr int B_    = 2;
constexpr int T_    = 2048;
constexpr int C_    = 2048;
constexpr int NH    = 16;
constexpr int NKV   = 4;
constexpr int HEADD = 128;
constexpr int GROUP = NH / NKV;     // 4
constexpr int KVC   = NKV * HEADD;  // 512
constexpr int M_    = B_ * T_;      // 4096
constexpr int NQKV  = C_ + 2 * KVC; // 3072

// ---------------- scratch ----------------
__device__ __half g_xh[(size_t)M_ * C_],  g_xl[(size_t)M_ * C_];
__device__ __half g_qh[(size_t)M_ * C_],  g_ql[(size_t)M_ * C_];
__device__ __half g_kh[(size_t)M_ * KVC];
__device__ __half g_vh[(size_t)M_ * KVC];
__device__ __half g_yh[(size_t)M_ * C_],  g_yl[(size_t)M_ * C_];
__device__ __half g_wh[(size_t)NQKV * C_];    // [n][k] k-major, Wq|Wk|Wv hi
__device__ __half g_woh[(size_t)C_ * C_];     // Wo hi, k-major

// ---------------- PTX helpers ----------------
__device__ __forceinline__ uint32_t smem_u32(const void* p) {
    uint32_t a;
    asm("{ .reg .u64 t; cvta.to.shared.u64 t, %1; cvt.u32.u64 %0, t; }" : "=r"(a) : "l"(p));
    return a;
}
#define CP_COMMIT()   asm volatile("cp.async.commit_group;" ::: "memory")
#define CP_WAIT(n)    asm volatile("cp.async.wait_group %0;" :: "n"(n) : "memory")
__device__ __forceinline__ void cp16(uint32_t dst, const void* src) {
    asm volatile("cp.async.cg.shared.global [%0], [%1], 16;" :: "r"(dst), "l"(src));
}
__device__ __forceinline__ void ldm_x4(uint32_t* r, uint32_t addr) {
    asm volatile("ldmatrix.sync.aligned.m8n8.x4.shared.b16 {%0,%1,%2,%3}, [%4];"
        : "=r"(r[0]), "=r"(r[1]), "=r"(r[2]), "=r"(r[3]) : "r"(addr));
}
__device__ __forceinline__ void ldm_x4_t(uint32_t* r, uint32_t addr) {
    asm volatile("ldmatrix.sync.aligned.m8n8.x4.trans.shared.b16 {%0,%1,%2,%3}, [%4];"
        : "=r"(r[0]), "=r"(r[1]), "=r"(r[2]), "=r"(r[3]) : "r"(addr));
}
__device__ __forceinline__ void mma16816(float* d, const uint32_t* a, uint32_t b0, uint32_t b1) {
    asm volatile("mma.sync.aligned.m16n8k16.row.col.f32.f16.f16.f32 "
        "{%0,%1,%2,%3}, {%4,%5,%6,%7}, {%8,%9}, {%0,%1,%2,%3};"
        : "+f"(d[0]), "+f"(d[1]), "+f"(d[2]), "+f"(d[3])
        : "r"(a[0]), "r"(a[1]), "r"(a[2]), "r"(a[3]), "r"(b0), "r"(b1));
}
__device__ __forceinline__ float fast_ex2(float x) {
    float y;
    asm("ex2.approx.f32 %0, %1;" : "=f"(y) : "f"(x));
    return y;
}
__device__ __forceinline__ uint32_t pack_h16(float a, float b) {
    __half2 v = __floats2half2_rn(a, b);
    return *(uint32_t*)&v;
}

// ---------------- conversion kernels ----------------
__global__ void split_kernel(const float* __restrict__ in, __half* __restrict__ hi,
                             __half* __restrict__ lo, int n4) {
    int i = blockIdx.x * 256 + threadIdx.x;
    if (i >= n4) return;
    float4 v = ((const float4*)in)[i];
    float vs[4] = {v.x, v.y, v.z, v.w};
    __half h[4], l[4];
    #pragma unroll
    for (int j = 0; j < 4; j++) {
        h[j] = __float2half_rn(vs[j]);
        l[j] = __float2half_rn(vs[j] - __half2float(h[j]));
    }
    ((__half2*)hi)[2 * i]     = __halves2half2(h[0], h[1]);
    ((__half2*)hi)[2 * i + 1] = __halves2half2(h[2], h[3]);
    ((__half2*)lo)[2 * i]     = __halves2half2(l[0], l[1]);
    ((__half2*)lo)[2 * i + 1] = __halves2half2(l[2], l[3]);
}

// fused transpose of Wq|Wk|Wv|Wo (K x N fp32, row-major) -> fp16 hi, k-major
__global__ void transpose_all_kernel(const float* __restrict__ Wq, const float* __restrict__ Wk,
                                     const float* __restrict__ Wv, const float* __restrict__ Wo,
                                     __half* __restrict__ wh, __half* __restrict__ woh) {
    __shared__ float tile[32][33];
    const int z = blockIdx.z;
    const float* W;
    __half* dst;
    int N, rowoff;
    if (z == 0)      { W = Wq; dst = wh;  N = C_;  rowoff = 0; }
    else if (z == 1) { W = Wk; dst = wh;  N = KVC; rowoff = C_; }
    else if (z == 2) { W = Wv; dst = wh;  N = KVC; rowoff = C_ + KVC; }
    else             { W = Wo; dst = woh; N = C_;  rowoff = 0; }

    int n0 = blockIdx.x * 32, k0 = blockIdx.y * 32;
    if (n0 >= N) return;
    int tx = threadIdx.x, ty = threadIdx.y;  // 32 x 8
    #pragma unroll
    for (int i = 0; i < 32; i += 8)
        tile[ty + i][tx] = W[(size_t)(k0 + ty + i) * N + n0 + tx];
    __syncthreads();
    #pragma unroll
    for (int i = 0; i < 32; i += 8)
        dst[(size_t)(rowoff + n0 + ty + i) * C_ + k0 + tx] = __float2half_rn(tile[tx][ty + i]);
}

// ---------------- 2-term fp16 GEMM via mma.sync, 3-stage pipeline ----------------
constexpr int BK        = 32;
constexpr int PITCH     = 80;
constexpr int TILE_BYT  = 128 * PITCH;        // 10240
constexpr int STAGE_BYT = 3 * TILE_BYT;       // Ah, Al, Bh = 30720
constexpr int GEMM_SMEM = 3 * STAGE_BYT;      // 92160 (3 stages)

// MODE 0: write fp32 Cf.  MODE 1: fused QKV epilogue.
template <int MODE>
__global__ __launch_bounds__(256, 2)
void tc_gemm(const __half* __restrict__ Ah, const __half* __restrict__ Al,
             const __half* __restrict__ Bh, float* __restrict__ Cf,
             __half* __restrict__ Qh, __half* __restrict__ Ql,
             __half* __restrict__ Kh, __half* __restrict__ Vh, int K) {
    extern __shared__ __align__(128) char smem[];
    const uint32_t sbase = smem_u32(smem);
    const int tid  = threadIdx.x;
    const int wid  = tid >> 5, lane = tid & 31;
    const int wm   = wid & 1;
    const int wn   = wid >> 1;
    const int m0   = blockIdx.y * 128, n0 = blockIdx.x * 128;

    const uint32_t aoff = (uint32_t)(lane & 15) * PITCH + (uint32_t)(lane >> 4) * 16;
    const uint32_t boff = (uint32_t)((lane & 7) + ((lane >> 4) & 1) * 8) * PITCH +
                          (uint32_t)((lane >> 3) & 1) * 16;

    float acc[4][4][4];
    #pragma unroll
    for (int i = 0; i < 4; i++)
        #pragma unroll
        for (int j = 0; j < 4; j++)
            #pragma unroll
            for (int q = 0; q < 4; q++) acc[i][j][q] = 0.f;

    const int NS = K / BK;
    const int lr = tid >> 2;
    const int lc = tid & 3;

    auto load_stage = [&](int s, int b) {
        uint32_t base = sbase + (uint32_t)b * STAGE_BYT;
        const int k0 = s * BK;
        const __half* srcs[3] = {Ah, Al, Bh};
        const int rows[3] = {m0, m0, n0};
        #pragma unroll
        for (int t = 0; t < 3; t++) {
            uint32_t tb = base + (uint32_t)t * TILE_BYT;
            #pragma unroll
            for (int p = 0; p < 2; p++) {
                int r = lr + p * 64;
                cp16(tb + (uint32_t)r * PITCH + (uint32_t)lc * 16,
                     (const char*)(srcs[t] + (size_t)(rows[t] + r) * K + k0) + lc * 16);
            }
        }
        CP_COMMIT();
    };

    load_stage(0, 0);
    load_stage(1, 1);

    for (int i = 0; i < NS; ++i) {
        const int buf = i % 3;
        // loads for stage i+2 write buffer (i+2)%3 == (i-1)%3; the end-of-iter
        // barrier of iteration i-1 guarantees all warps finished reading it.
        if (i + 2 < NS)      { load_stage(i + 2, (i + 2) % 3); CP_WAIT(2); }
        else if (i + 1 < NS) { CP_WAIT(1); }
        else                 { CP_WAIT(0); }
        __syncthreads();

        const uint32_t base = sbase + (uint32_t)buf * STAGE_BYT;
        const uint32_t aH = base, aL = base + TILE_BYT, bH = base + 2 * TILE_BYT;
        const uint32_t arow = (uint32_t)(wm * 64) * PITCH;
        const uint32_t brow = (uint32_t)(wn * 32) * PITCH;

        #pragma unroll
        for (int kk = 0; kk < 2; ++kk) {
            const uint32_t kb = (uint32_t)kk * 32;
            uint32_t ah[4][4], al[4][4], bf[4][2];

            #pragma unroll
            for (int mi = 0; mi < 4; mi++)
                ldm_x4(ah[mi], aH + arow + (uint32_t)(mi * 16) * PITCH + kb + aoff);
            #pragma unroll
            for (int mi = 0; mi < 4; mi++)
                ldm_x4(al[mi], aL + arow + (uint32_t)(mi * 16) * PITCH + kb + aoff);
            #pragma unroll
            for (int np = 0; np < 2; np++) {
                uint32_t t[4];
                ldm_x4(t, bH + brow + (uint32_t)(np * 16) * PITCH + kb + boff);
                bf[2 * np][0] = t[0]; bf[2 * np][1] = t[1];
                bf[2 * np + 1][0] = t[2]; bf[2 * np + 1][1] = t[3];
            }
            #pragma unroll
            for (int mi = 0; mi < 4; mi++)
                #pragma unroll
                for (int ni = 0; ni < 4; ni++) {
                    mma16816(acc[mi][ni], ah[mi], bf[ni][0], bf[ni][1]);
                    mma16816(acc[mi][ni], al[mi], bf[ni][0], bf[ni][1]);
                }
        }
        __syncthreads();
    }

    const int rbase = m0 + wm * 64 + (lane >> 2);
    const int cbase = n0 + wn * 32 + (lane & 3) * 2;
    #pragma unroll
    for (int mi = 0; mi < 4; mi++) {
        #pragma unroll
        for (int ni = 0; ni < 4; ni++) {
            int col = cbase + ni * 8;
            #pragma unroll
            for (int half = 0; half < 2; half++) {
                int row = rbase + mi * 16 + half * 8;
                float v0 = acc[mi][ni][2 * half], v1 = acc[mi][ni][2 * half + 1];
                if (MODE == 0) {
                    *(float2*)&Cf[(size_t)row * C_ + col] = make_float2(v0, v1);
                } else {
                    if (col < C_) {          // Q: split hi/lo
                        __half h0 = __float2half_rn(v0), h1 = __float2half_rn(v1);
                        __half l0 = __float2half_rn(v0 - __half2float(h0));
                        __half l1 = __float2half_rn(v1 - __half2float(h1));
                        *(__half2*)&Qh[(size_t)row * C_ + col] = __halves2half2(h0, h1);
                        *(__half2*)&Ql[(size_t)row * C_ + col] = __halves2half2(l0, l1);
                    } else if (col < C_ + KVC) {
                        *(__half2*)&Kh[(size_t)row * KVC + (col - C_)] =
                            __floats2half2_rn(v0, v1);
                    } else {
                        *(__half2*)&Vh[(size_t)row * KVC + (col - C_ - KVC)] =
                            __floats2half2_rn(v0, v1);
                    }
                }
            }
        }
    }
}

// ---------------- tensor-core causal GQA flash attention (fp16) ----------------
// CTA: 64 q rows, 4 warps x 16 rows, 128 threads. K-tile 64 keys. occ 2.
constexpr int APITCH  = 272;
constexpr int AT_TILE = 64 * APITCH;          // 17408
constexpr int AT_SMEM = 2 * AT_TILE;          // 34816

__global__ __launch_bounds__(128, 2)
void attn_mma(const __half* __restrict__ Qh, const __half* __restrict__ Ql,
              const __half* __restrict__ Kh, const __half* __restrict__ Vh,
              __half* __restrict__ Yh, __half* __restrict__ Yl) {
    extern __shared__ __align__(128) char smem[];
    const uint32_t sb = smem_u32(smem);
    const uint32_t KH = sb, VH = sb + AT_TILE;

    const int qi = gridDim.x - 1 - blockIdx.x;     // heavy CTAs first
    const int h = blockIdx.y, b = blockIdx.z;
    const int kvh = h / GROUP;
    const int q0  = qi * 64;
    const int tid = threadIdx.x, wid = tid >> 5, lane = tid & 31;

    const uint32_t aoff = (uint32_t)(lane & 15) * APITCH + (uint32_t)(lane >> 4) * 16;
    const uint32_t boff = (uint32_t)((lane & 7) + ((lane >> 3) & 1) * 8) * APITCH +
                          (uint32_t)(lane >> 4) * 16;
    const float SCL2 = 0.127517408f;  // (1/sqrt(128)) * log2(e)

    // ---- stage Q hi then lo through KH area, grab frags ----
    uint32_t qfh[8][4], qfl[8][4];
    {
        const __half* gq[2] = {Qh + ((size_t)(b * T_ + q0)) * C_ + h * HEADD,
                               Ql + ((size_t)(b * T_ + q0)) * C_ + h * HEADD};
        #pragma unroll
        for (int pass = 0; pass < 2; pass++) {
            #pragma unroll
            for (int i = 0; i < 8; i++) {
                int idx = tid + i * 128;              // 0..1023
                int row = idx >> 4, ch = idx & 15;
                cp16(KH + (uint32_t)row * APITCH + (uint32_t)ch * 16,
                     (const char*)(gq[pass] + (size_t)row * C_) + ch * 16);
            }
            CP_COMMIT(); CP_WAIT(0);
            __syncthreads();
            #pragma unroll
            for (int kb = 0; kb < 8; kb++) {
                uint32_t* dst = (pass == 0) ? qfh[kb] : qfl[kb];
                ldm_x4(dst, KH + (uint32_t)(wid * 16) * APITCH + (uint32_t)kb * 32 + aoff);
            }
            __syncthreads();
        }
    }

    float o[16][4];
    #pragma unroll
    for (int i = 0; i < 16; i++)
        #pragma unroll
        for (int q = 0; q < 4; q++) o[i][q] = 0.f;
    float m0 = -1e30f, m1 = -1e30f, l0 = 0.f, l1 = 0.f;

    const int ntiles = qi + 1;

    auto load_K = [&](int j) {
        const size_t gb = ((size_t)(b * T_ + j * 64)) * KVC + kvh * HEADD;
        #pragma unroll
        for (int i = 0; i < 8; i++) {
            int idx = tid + i * 128;                  // 0..1023
            int row = idx >> 4, ch = idx & 15;
            cp16(KH + (uint32_t)row * APITCH + (uint32_t)ch * 16,
                 (const char*)(Kh + gb + (size_t)row * KVC) + ch * 16);
        }
        CP_COMMIT();
    };
    auto load_V = [&](int j) {
        const size_t gb = ((size_t)(b * T_ + j * 64)) * KVC + kvh * HEADD;
        #pragma unroll
        for (int i = 0; i < 8; i++) {
            int idx = tid + i * 128;
            int row = idx >> 4, ch = idx & 15;
            cp16(VH + (uint32_t)row * APITCH + (uint32_t)ch * 16,
                 (const char*)(Vh + gb + (size_t)row * KVC) + ch * 16);
        }
        CP_COMMIT();
    };

    load_K(0);
    load_V(0);
    CP_WAIT(1);          // K0 done, V0 in flight
    __syncthreads();

    const int row0 = q0 + wid * 16 + (lane >> 2);
    const int row1 = row0 + 8;

    for (int j = 0; j < ntiles; j++) {
        // ---------- scores S = (Qh+Ql) Kh^T ----------
        float s[8][4];
        #pragma unroll
        for (int nb = 0; nb < 8; nb++)
            #pragma unroll
            for (int q = 0; q < 4; q++) s[nb][q] = 0.f;

        #pragma unroll
        for (int kb = 0; kb < 8; kb++) {
            uint32_t kf[4][4];
            #pragma unroll
            for (int kg = 0; kg < 4; kg++)
                ldm_x4(kf[kg], KH + (uint32_t)(kg * 16) * APITCH + (uint32_t)kb * 32 + boff);
            #pragma unroll
            for (int nb = 0; nb < 8; nb++) {
                mma16816(s[nb], qfh[kb], kf[nb >> 1][nb & 1], kf[nb >> 1][(nb & 1) + 2]);
                mma16816(s[nb], qfl[kb], kf[nb >> 1][nb & 1], kf[nb >> 1][(nb & 1) + 2]);
            }
        }
        __syncthreads();                     // all warps done reading K[j]
        if (j + 1 < ntiles) { load_K(j + 1); CP_WAIT(1); }  // V[j] done, K[j+1] in flight
        else                { CP_WAIT(0); }
        __syncthreads();

        // ---------- online softmax ----------
        const int k0 = j * 64;
        const bool masked = (j == qi);
        float mt0 = -1e30f, mt1 = -1e30f;
        #pragma unroll
        for (int nb = 0; nb < 8; nb++) {
            #pragma unroll
            for (int q = 0; q < 4; q++) {
                float v = s[nb][q] * SCL2;
                if (masked) {
                    int key = k0 + nb * 8 + (lane & 3) * 2 + (q & 1);
                    int qr  = (q < 2) ? row0 : row1;
                    if (key > qr) v = -1e30f;
                }
                s[nb][q] = v;
                if (q < 2) mt0 = fmaxf(mt0, v); else mt1 = fmaxf(mt1, v);
            }
        }
        mt0 = fmaxf(mt0, __shfl_xor_sync(0xffffffffu, mt0, 1));
        mt0 = fmaxf(mt0, __shfl_xor_sync(0xffffffffu, mt0, 2));
        mt1 = fmaxf(mt1, __shfl_xor_sync(0xffffffffu, mt1, 1));
        mt1 = fmaxf(mt1, __shfl_xor_sync(0xffffffffu, mt1, 2));

        float m0n = fmaxf(m0, mt0), m1n = fmaxf(m1, mt1);
        float c0 = fast_ex2(m0 - m0n), c1 = fast_ex2(m1 - m1n);
        m0 = m0n; m1 = m1n;

        float lt0 = 0.f, lt1 = 0.f;
        #pragma unroll
        for (int nb = 0; nb < 8; nb++) {
            #pragma unroll
            for (int q = 0; q < 4; q++) {
                float p = fast_ex2(s[nb][q] - ((q < 2) ? m0 : m1));
                s[nb][q] = p;
                if (q < 2) lt0 += p; else lt1 += p;
            }
        }
        l0 = l0 * c0 + lt0;
        l1 = l1 * c1 + lt1;
        #pragma unroll
        for (int ob = 0; ob < 16; ob++) {
            o[ob][0] *= c0; o[ob][1] *= c0;
            o[ob][2] *= c1; o[ob][3] *= c1;
        }

        // ---------- PV: O += Ph * Vh ----------
        #pragma unroll
        for (int kb2 = 0; kb2 < 4; kb2++) {
            uint32_t pah[4];
            #pragma unroll
            for (int half = 0; half < 2; half++) {
                int nb = 2 * kb2 + half;
                pah[2 * half]     = pack_h16(s[nb][0], s[nb][1]);
                pah[2 * half + 1] = pack_h16(s[nb][2], s[nb][3]);
            }
            #pragma unroll
            for (int dg = 0; dg < 8; dg++) {
                uint32_t vf[4];
                ldm_x4_t(vf, VH + (uint32_t)(kb2 * 16) * APITCH + (uint32_t)dg * 32 + boff);
                mma16816(o[2 * dg],     pah, vf[0], vf[1]);
                mma16816(o[2 * dg + 1], pah, vf[2], vf[3]);
            }
        }
        __syncthreads();                     // all warps done reading V[j]
        if (j + 1 < ntiles) { load_V(j + 1); CP_WAIT(1); }  // K[j+1] done, V[j+1] in flight
        else                { CP_WAIT(0); }
        __syncthreads();
    }

    // ---------- epilogue ----------
    l0 += __shfl_xor_sync(0xffffffffu, l0, 1);
    l0 += __shfl_xor_sync(0xffffffffu, l0, 2);
    l1 += __shfl_xor_sync(0xffffffffu, l1, 1);
    l1 += __shfl_xor_sync(0xffffffffu, l1, 2);
    const float i0 = 1.f / l0, i1 = 1.f / l1;

    #pragma unroll
    for (int ob = 0; ob < 16; ob++) {
        const int col = h * HEADD + ob * 8 + (lane & 3) * 2;
        #pragma unroll
        for (int half = 0; half < 2; half++) {
            const int rr = (half == 0) ? row0 : row1;
            const float sc = (half == 0) ? i0 : i1;
            float y0 = o[ob][2 * half] * sc, y1 = o[ob][2 * half + 1] * sc;
            __half h0 = __float2half_rn(y0), h1 = __float2half_rn(y1);
            __half e0 = __float2half_rn(y0 - __half2float(h0));
            __half e1 = __float2half_rn(y1 - __half2float(h1));
            size_t off = (size_t)(b * T_ + rr) * C_ + col;
            *(__half2*)&Yh[off] = __halves2half2(h0, h1);
            *(__half2*)&Yl[off] = __halves2half2(e0, e1);
        }
    }
}

// ---------------- launch ----------------
extern "C" void kernel_launch(void* const* d_in, const int* in_sizes, int n_in,
                              void* d_out, int out_size) {
    const float* x  = (const float*)d_in[0];
    const float* Wq = (const float*)d_in[1];
    const float* Wk = (const float*)d_in[2];
    const float* Wv = (const float*)d_in[3];
    const float* Wo = (const float*)d_in[4];
    float* out = (float*)d_out;

    __half *xh, *xl, *qh, *ql, *kh, *vh, *yh, *yl, *wh, *woh;
    cudaGetSymbolAddress((void**)&xh, g_xh);   cudaGetSymbolAddress((void**)&xl, g_xl);
    cudaGetSymbolAddress((void**)&qh, g_qh);   cudaGetSymbolAddress((void**)&ql, g_ql);
    cudaGetSymbolAddress((void**)&kh, g_kh);   cudaGetSymbolAddress((void**)&vh, g_vh);
    cudaGetSymbolAddress((void**)&yh, g_yh);   cudaGetSymbolAddress((void**)&yl, g_yl);
    cudaGetSymbolAddress((void**)&wh, g_wh);   cudaGetSymbolAddress((void**)&woh, g_woh);

    cudaFuncSetAttribute(tc_gemm<0>, cudaFuncAttributeMaxDynamicSharedMemorySize, GEMM_SMEM);
    cudaFuncSetAttribute(tc_gemm<1>, cudaFuncAttributeMaxDynamicSharedMemorySize, GEMM_SMEM);
    cudaFuncSetAttribute(attn_mma, cudaFuncAttributeMaxDynamicSharedMemorySize, AT_SMEM);

    // 1) conversions
    {
        int n4 = M_ * C_ / 4;
        split_kernel<<<(n4 + 255) / 256, 256>>>(x, xh, xl, n4);
        transpose_all_kernel<<<dim3(C_ / 32, C_ / 32, 4), dim3(32, 8)>>>(
            Wq, Wk, Wv, Wo, wh, woh);
    }

    dim3 blk(256);
    // 2) fused QKV projection
    tc_gemm<1><<<dim3(NQKV / 128, M_ / 128), blk, GEMM_SMEM>>>(
        xh, xl, wh, nullptr, qh, ql, kh, vh, C_);

    // 3) attention (64-row CTAs, occ 2, heavy-first)
    attn_mma<<<dim3(T_ / 64, NH, B_), dim3(128), AT_SMEM>>>(qh, ql, kh, vh, yh, yl);

    // 4) output projection
    tc_gemm<0><<<dim3(C_ / 128, M_ / 128), blk, GEMM_SMEM>>>(
        yh, yl, woh, out, nullptr, nullptr, nullptr, nullptr, C_);
}